// round 4
// baseline (speedup 1.0000x reference)
#include <cuda_runtime.h>
#include <math.h>

#define BB 2
#define NN 512
#define QDIM 512
#define EDIM 11
#define NH 4
#define DHEAD 64
#define DIN 256          // INNER = NH*DHEAD
#define SCALE_F 0.125f   // 64^-0.5

#define ITILE 8
#define JTILE 32

// -------- device scratch (no allocations allowed) --------
__device__ float g_q[BB * NN * DIN];
__device__ float g_k[BB * NN * DIN];
__device__ float g_v[BB * NN * DIN];
__device__ float g_oi[BB * NN * DIN];
__device__ float g_attn_scratch[BB * NH * NN * NN];  // fallback if harness only wants `out`
__device__ unsigned char g_mask[BB * NN * NN];
__device__ int g_mask_mode;   // 0 = int32, 1 = float32, 2 = uint8/bool

__device__ __forceinline__ float gelu_exact(float x) {
    return 0.5f * x * (1.0f + erff(x * 0.70710678118654752f));
}

// ============================================================
// Mask dtype sniffing + canonicalization.
// Reads only the first n_elems BYTES (in-bounds for every candidate dtype).
//  - int32 storage  : all u32 words in {0,1}
//  - float32 storage: words in {0, 0x3F800000}
//  - uint8 storage  : words with 0/1 bytes -> many values >1 (and never 0x3F800000)
// ============================================================
__global__ void detect_mask_kernel(const unsigned int* __restrict__ w, int nwords) {
    __shared__ int s_weird, s_float;
    if (threadIdx.x == 0) { s_weird = 0; s_float = 0; }
    __syncthreads();
    int weird = 0, flt = 0;
    for (int i = threadIdx.x; i < nwords; i += blockDim.x) {
        unsigned int v = w[i];
        if (v == 0x3F800000u) flt = 1;
        else if (v > 1u) weird = 1;
    }
    if (weird) atomicOr(&s_weird, 1);
    if (flt)   atomicOr(&s_float, 1);
    __syncthreads();
    if (threadIdx.x == 0)
        g_mask_mode = s_weird ? 2 : (s_float ? 1 : 0);
}

__global__ void canon_mask_kernel(const void* __restrict__ raw, int n) {
    const int mode = g_mask_mode;
    for (int i = blockIdx.x * blockDim.x + threadIdx.x; i < n; i += gridDim.x * blockDim.x) {
        unsigned char m;
        if (mode == 2)      m = (((const unsigned char*)raw)[i] != 0);
        else if (mode == 1) m = (((const float*)raw)[i] != 0.0f);
        else                m = (((const unsigned int*)raw)[i] != 0u);
        g_mask[i] = m;
    }
}

// ============================================================
// Generic tiled GEMM: C[M,Nc] = A[M,K] @ W[K,Nc] (+ bias[n])
// 64x64 block tile, 256 threads, 4x4 per thread, K-tile 16.
// ============================================================
__global__ __launch_bounds__(256) void gemm_tiled(
    const float* __restrict__ A, const float* __restrict__ W,
    const float* __restrict__ bias, float* __restrict__ C,
    int M, int K, int Nc)
{
    __shared__ float As[16][65];
    __shared__ float Bs[16][65];
    const int t = threadIdx.x;
    const int r = t >> 4, c = t & 15;
    const int m0 = blockIdx.y * 64, n0 = blockIdx.x * 64;
    float acc[4][4] = {};

    for (int k0 = 0; k0 < K; k0 += 16) {
        #pragma unroll
        for (int l = 0; l < 4; l++) {
            int idx = t + l * 256;
            int mm = idx >> 4, kk = idx & 15;
            As[kk][mm] = A[(m0 + mm) * K + (k0 + kk)];
            int kk2 = idx >> 6, nn = idx & 63;
            Bs[kk2][nn] = W[(k0 + kk2) * Nc + (n0 + nn)];
        }
        __syncthreads();
        #pragma unroll
        for (int kk = 0; kk < 16; kk++) {
            float av[4], bv[4];
            #pragma unroll
            for (int l = 0; l < 4; l++) av[l] = As[kk][r * 4 + l];
            #pragma unroll
            for (int l = 0; l < 4; l++) bv[l] = Bs[kk][c * 4 + l];
            #pragma unroll
            for (int i = 0; i < 4; i++)
                #pragma unroll
                for (int j = 0; j < 4; j++)
                    acc[i][j] += av[i] * bv[j];
        }
        __syncthreads();
    }

    #pragma unroll
    for (int i = 0; i < 4; i++)
        #pragma unroll
        for (int j = 0; j < 4; j++) {
            int m = m0 + r * 4 + i, n = n0 + c * 4 + j;
            float v = acc[i][j];
            if (bias) v += bias[n];
            C[m * Nc + n] = v;
        }
}

// ============================================================
// Fused attention: per block (b, 8 query rows).
//  pass1: sim = q.kT*scale + bias-MLP(edge_attr), masked
//  pass2: softmax -> attn (shared + global output)
//  pass3: t = sum_j attn * gelu(e@Wev1+bev1);  vacc = attn@v
//  final: o_inner = vacc + t@Wev2 + bev2
// ============================================================
__global__ __launch_bounds__(256, 1) void attn_fused(
    const float* __restrict__ edge_attr,
    const unsigned char* __restrict__ mask,
    const float* __restrict__ Web1, const float* __restrict__ beb1,
    const float* __restrict__ Web2, const float* __restrict__ beb2,
    const float* __restrict__ Wev1, const float* __restrict__ bev1,
    const float* __restrict__ Wev2, const float* __restrict__ bev2,
    float* __restrict__ attn_out)
{
    extern __shared__ float sm[];
    float* qs   = sm;                          // 8*256   = 2048
    float* S    = sm + 2048;                   // 8*4*512 = 16384
    float* tsh  = sm + 2048 + 16384;           // 8*4*256 = 8192
    float* vacc = sm + 2048 + 16384 + 8192;    // 8*256   = 2048
    float* esh  = sm + 28672;                  // 8*32*11 = 2816
    float* kvs  = sm + 31488;                  // 32*256  = 8192
    // total 39680 floats = 158720 bytes

    const int t = threadIdx.x;
    const int warp = t >> 5, lane = t & 31;
    const int b = blockIdx.y;
    const int i0 = blockIdx.x * ITILE;
    const int ii = warp;  // one warp per query row in the tile

    // ---- stage q rows for this i-tile (2048 floats, contiguous) ----
    {
        const float4* src = (const float4*)&g_q[(b * NN + i0) * DIN];
        float4* dst = (float4*)qs;
        #pragma unroll
        for (int l = 0; l < 2; l++) dst[t + l * 256] = src[t + l * 256];
    }

    // ---- per-lane weight registers for the bias MLP ----
    float W1r[EDIM][8], b1r[8], W2r[8][4];
    #pragma unroll
    for (int c8 = 0; c8 < 8; c8++) {
        int cc = lane + 32 * c8;
        b1r[c8] = beb1[cc];
        #pragma unroll
        for (int a = 0; a < EDIM; a++) W1r[a][c8] = Web1[a * DIN + cc];
        #pragma unroll
        for (int h = 0; h < NH; h++) W2r[c8][h] = Web2[cc * NH + h];
    }
    const float b2r0 = beb2[0], b2r1 = beb2[1], b2r2 = beb2[2], b2r3 = beb2[3];
    __syncthreads();

    // =================== PASS 1: sim + edge bias ===================
    for (int jt = 0; jt < NN; jt += JTILE) {
        // stage k tile: 32 rows x 256 = 8192 floats, contiguous in g_k
        {
            const float4* src = (const float4*)&g_k[(b * NN + jt) * DIN];
            float4* dst = (float4*)kvs;
            #pragma unroll
            for (int l = 0; l < 8; l++) dst[t + l * 256] = src[t + l * 256];
        }
        for (int idx = t; idx < ITILE * JTILE * EDIM; idx += 256) {
            int e_ii = idx / (JTILE * EDIM);
            int rem  = idx - e_ii * (JTILE * EDIM);
            esh[idx] = edge_attr[((size_t)(b * NN + i0 + e_ii) * NN + jt) * EDIM + rem];
        }
        __syncthreads();

        for (int jj = 0; jj < JTILE; jj++) {
            const int j = jt + jj;
            const unsigned char mk = mask[(b * NN + i0 + ii) * NN + j];
            if (!mk) {
                if (lane < NH) S[(ii * NH + lane) * NN + j] = -3.402823466e38f;
                continue;
            }
            float e[EDIM];
            #pragma unroll
            for (int a = 0; a < EDIM; a++) e[a] = esh[(ii * JTILE + jj) * EDIM + a];

            // q.k partials (lane covers d=lane, lane+32 for each head)
            const float* kr = kvs + jj * DIN;
            const float* qr = qs + ii * DIN;
            float red0 = SCALE_F * (qr[lane] * kr[lane] + qr[lane + 32] * kr[lane + 32]);
            float red1 = SCALE_F * (qr[64 + lane] * kr[64 + lane] + qr[96 + lane] * kr[96 + lane]);
            float red2 = SCALE_F * (qr[128 + lane] * kr[128 + lane] + qr[160 + lane] * kr[160 + lane]);
            float red3 = SCALE_F * (qr[192 + lane] * kr[192 + lane] + qr[224 + lane] * kr[224 + lane]);

            // bias MLP: 8 hidden channels per lane
            #pragma unroll
            for (int c8 = 0; c8 < 8; c8++) {
                float s = b1r[c8];
                #pragma unroll
                for (int a = 0; a < EDIM; a++) s += e[a] * W1r[a][c8];
                float g = gelu_exact(s);
                red0 += g * W2r[c8][0];
                red1 += g * W2r[c8][1];
                red2 += g * W2r[c8][2];
                red3 += g * W2r[c8][3];
            }
            #pragma unroll
            for (int off = 16; off > 0; off >>= 1) {
                red0 += __shfl_xor_sync(0xffffffffu, red0, off);
                red1 += __shfl_xor_sync(0xffffffffu, red1, off);
                red2 += __shfl_xor_sync(0xffffffffu, red2, off);
                red3 += __shfl_xor_sync(0xffffffffu, red3, off);
            }
            if (lane < 4) {
                float v  = (lane == 0) ? red0 : (lane == 1) ? red1 : (lane == 2) ? red2 : red3;
                float bb = (lane == 0) ? b2r0 : (lane == 1) ? b2r1 : (lane == 2) ? b2r2 : b2r3;
                S[(ii * NH + lane) * NN + j] = v + bb;
            }
        }
        __syncthreads();
    }

    // =================== PASS 2: softmax ===================
    #pragma unroll
    for (int rr = 0; rr < 4; rr++) {
        const int row = warp * 4 + rr;       // == ii*4 + h
        const int rii = row >> 2, h = row & 3;
        float vals[16];
        float m = -3.402823466e38f;
        #pragma unroll
        for (int kk = 0; kk < 16; kk++) {
            vals[kk] = S[row * NN + lane + kk * 32];
            m = fmaxf(m, vals[kk]);
        }
        #pragma unroll
        for (int off = 16; off > 0; off >>= 1)
            m = fmaxf(m, __shfl_xor_sync(0xffffffffu, m, off));
        float sum = 0.f;
        #pragma unroll
        for (int kk = 0; kk < 16; kk++) {
            float p = __expf(vals[kk] - m);
            vals[kk] = p;
            sum += p;
        }
        #pragma unroll
        for (int off = 16; off > 0; off >>= 1)
            sum += __shfl_xor_sync(0xffffffffu, sum, off);
        const float inv = 1.0f / sum;
        float* arow = attn_out + (((size_t)b * NH + h) * NN + (i0 + rii)) * NN;
        #pragma unroll
        for (int kk = 0; kk < 16; kk++) {
            float a = vals[kk] * inv;
            S[row * NN + lane + kk * 32] = a;
            arow[lane + kk * 32] = a;
        }
    }
    __syncthreads();

    // =================== PASS 3: t and attn@v accumulation ===================
    #pragma unroll
    for (int c8 = 0; c8 < 8; c8++) {
        int cc = lane + 32 * c8;
        b1r[c8] = bev1[cc];
        #pragma unroll
        for (int a = 0; a < EDIM; a++) W1r[a][c8] = Wev1[a * DIN + cc];
    }
    float tr[NH][8];
    float va[NH][2];
    #pragma unroll
    for (int h = 0; h < NH; h++) {
        #pragma unroll
        for (int c8 = 0; c8 < 8; c8++) tr[h][c8] = 0.f;
        va[h][0] = 0.f; va[h][1] = 0.f;
    }

    for (int jt = 0; jt < NN; jt += JTILE) {
        // stage v tile: 32 rows x 256 = 8192 floats, contiguous in g_v
        {
            const float4* src = (const float4*)&g_v[(b * NN + jt) * DIN];
            float4* dst = (float4*)kvs;
            #pragma unroll
            for (int l = 0; l < 8; l++) dst[t + l * 256] = src[t + l * 256];
        }
        for (int idx = t; idx < ITILE * JTILE * EDIM; idx += 256) {
            int e_ii = idx / (JTILE * EDIM);
            int rem  = idx - e_ii * (JTILE * EDIM);
            esh[idx] = edge_attr[((size_t)(b * NN + i0 + e_ii) * NN + jt) * EDIM + rem];
        }
        __syncthreads();

        for (int jj = 0; jj < JTILE; jj++) {
            const int j = jt + jj;
            const float a0 = S[(ii * NH + 0) * NN + j];
            const float a1 = S[(ii * NH + 1) * NN + j];
            const float a2 = S[(ii * NH + 2) * NN + j];
            const float a3 = S[(ii * NH + 3) * NN + j];
            if (a0 + a1 + a2 + a3 == 0.f) continue;  // masked column: exact zeros

            float e[EDIM];
            #pragma unroll
            for (int a = 0; a < EDIM; a++) e[a] = esh[(ii * JTILE + jj) * EDIM + a];

            #pragma unroll
            for (int c8 = 0; c8 < 8; c8++) {
                float s = b1r[c8];
                #pragma unroll
                for (int a = 0; a < EDIM; a++) s += e[a] * W1r[a][c8];
                float g = gelu_exact(s);
                tr[0][c8] += a0 * g;
                tr[1][c8] += a1 * g;
                tr[2][c8] += a2 * g;
                tr[3][c8] += a3 * g;
            }
            const float* vr = kvs + jj * DIN;
            va[0][0] += a0 * vr[lane];        va[0][1] += a0 * vr[lane + 32];
            va[1][0] += a1 * vr[64 + lane];   va[1][1] += a1 * vr[96 + lane];
            va[2][0] += a2 * vr[128 + lane];  va[2][1] += a2 * vr[160 + lane];
            va[3][0] += a3 * vr[192 + lane];  va[3][1] += a3 * vr[224 + lane];
        }
        __syncthreads();
    }

    // dump register accumulators to shared
    #pragma unroll
    for (int h = 0; h < NH; h++) {
        #pragma unroll
        for (int c8 = 0; c8 < 8; c8++)
            tsh[(ii * NH + h) * DIN + lane + 32 * c8] = tr[h][c8];
        vacc[ii * DIN + h * 64 + lane]      = va[h][0];
        vacc[ii * DIN + h * 64 + lane + 32] = va[h][1];
    }
    __syncthreads();

    // =================== FINAL: o_inner = vacc + t@Wev2 + bev2 ===================
    {
        const int col = t;
        const int h = col >> 6;
        const float bcol = bev2[col];
        for (int i2 = 0; i2 < ITILE; i2++) {
            const float* trow = &tsh[(i2 * NH + h) * DIN];
            float acc0 = 0.f, acc1 = 0.f, acc2 = 0.f, acc3 = 0.f;
            #pragma unroll 4
            for (int cc = 0; cc < DIN; cc += 4) {
                acc0 += trow[cc]     * Wev2[(cc)     * DIN + col];
                acc1 += trow[cc + 1] * Wev2[(cc + 1) * DIN + col];
                acc2 += trow[cc + 2] * Wev2[(cc + 2) * DIN + col];
                acc3 += trow[cc + 3] * Wev2[(cc + 3) * DIN + col];
            }
            g_oi[(b * NN + i0 + i2) * DIN + col] =
                ((acc0 + acc1) + (acc2 + acc3)) + vacc[i2 * DIN + col] + bcol;
        }
    }
}

// ============================================================
extern "C" void kernel_launch(void* const* d_in, const int* in_sizes, int n_in,
                              void* d_out, int out_size)
{
    const float* x           = (const float*)d_in[0];
    const void*  mask_raw    = d_in[1];
    const float* ea          = (const float*)d_in[2];
    const float* Wq          = (const float*)d_in[3];
    const float* Wk          = (const float*)d_in[4];
    const float* Wv          = (const float*)d_in[5];
    const float* Web1        = (const float*)d_in[6];
    const float* beb1        = (const float*)d_in[7];
    const float* Web2        = (const float*)d_in[8];
    const float* beb2        = (const float*)d_in[9];
    const float* Wev1        = (const float*)d_in[10];
    const float* bev1        = (const float*)d_in[11];
    const float* Wev2        = (const float*)d_in[12];
    const float* bev2        = (const float*)d_in[13];
    const float* Wo          = (const float*)d_in[14];
    const float* bo          = (const float*)d_in[15];

    float* out = (float*)d_out;
    const int out_elems  = BB * NN * QDIM;              // 524288
    const int attn_elems = BB * NH * NN * NN;           // 2097152
    const int mask_elems = BB * NN * NN;                // 524288

    float *qp, *kp, *vp, *oip, *attn_fb;
    unsigned char* maskp;
    cudaGetSymbolAddress((void**)&qp,  g_q);
    cudaGetSymbolAddress((void**)&kp,  g_k);
    cudaGetSymbolAddress((void**)&vp,  g_v);
    cudaGetSymbolAddress((void**)&oip, g_oi);
    cudaGetSymbolAddress((void**)&attn_fb, g_attn_scratch);
    cudaGetSymbolAddress((void**)&maskp, g_mask);

    // attn is the second element of the reference's returned tuple; if the
    // harness output only holds `out`, keep attn in device scratch.
    float* attn = (out_size >= out_elems + attn_elems) ? (out + out_elems) : attn_fb;

    const int smem_bytes = 39680 * 4;
    cudaFuncSetAttribute(attn_fused, cudaFuncAttributeMaxDynamicSharedMemorySize, smem_bytes);

    // mask dtype sniff + canonicalize to uint8
    detect_mask_kernel<<<1, 256>>>((const unsigned int*)mask_raw, mask_elems / 4);
    canon_mask_kernel<<<256, 256>>>(mask_raw, mask_elems);

    // q/k/v projections
    gemm_tiled<<<dim3(DIN / 64, (BB * NN) / 64), 256>>>(x, Wq, nullptr, qp, BB * NN, QDIM, DIN);
    gemm_tiled<<<dim3(DIN / 64, (BB * NN) / 64), 256>>>(x, Wk, nullptr, kp, BB * NN, QDIM, DIN);
    gemm_tiled<<<dim3(DIN / 64, (BB * NN) / 64), 256>>>(x, Wv, nullptr, vp, BB * NN, QDIM, DIN);

    // fused attention + edge MLPs
    attn_fused<<<dim3(NN / ITILE, BB), 256, smem_bytes>>>(
        ea, maskp, Web1, beb1, Web2, beb2, Wev1, bev1, Wev2, bev2, attn);

    // final projection: out = o_inner @ Wo + bo
    gemm_tiled<<<dim3(QDIM / 64, (BB * NN) / 64), 256>>>(oip, Wo, bo, out, BB * NN, DIN, QDIM);
}

// round 5
// speedup vs baseline: 1.5900x; 1.5900x over previous
#include <cuda_runtime.h>
#include <math.h>

#define BB 2
#define NN 512
#define QDIM 512
#define EDIM 11
#define NH 4
#define DHEAD 64
#define DIN 256          // INNER = NH*DHEAD
#define SCALE_F 0.125f   // 64^-0.5
#define NEGMAX -3.402823466e38f

#define ITILE 8
#define JTILE 32

// -------- device scratch (no allocations allowed) --------
__device__ float g_q[BB * NN * DIN];
__device__ float g_k[BB * NN * DIN];
__device__ float g_v[BB * NN * DIN];
__device__ float g_oi[BB * NN * DIN];
__device__ float g_attn_scratch[BB * NH * NN * NN];
__device__ unsigned char g_mask[BB * NN * NN];
__device__ int g_mask_mode;   // 0 = int32, 1 = float32, 2 = uint8/bool

__device__ __forceinline__ float gelu_exact(float x) {
    return 0.5f * x * (1.0f + erff(x * 0.70710678118654752f));
}

// ============================================================
// Mask dtype sniffing + canonicalization (proven in round 4).
// ============================================================
__global__ void detect_mask_kernel(const unsigned int* __restrict__ w, int nwords) {
    __shared__ int s_weird, s_float;
    if (threadIdx.x == 0) { s_weird = 0; s_float = 0; }
    __syncthreads();
    int weird = 0, flt = 0;
    for (int i = threadIdx.x; i < nwords; i += blockDim.x) {
        unsigned int v = w[i];
        if (v == 0x3F800000u) flt = 1;
        else if (v > 1u) weird = 1;
    }
    if (weird) atomicOr(&s_weird, 1);
    if (flt)   atomicOr(&s_float, 1);
    __syncthreads();
    if (threadIdx.x == 0)
        g_mask_mode = s_weird ? 2 : (s_float ? 1 : 0);
}

__global__ void canon_mask_kernel(const void* __restrict__ raw, int n) {
    const int mode = g_mask_mode;
    for (int i = blockIdx.x * blockDim.x + threadIdx.x; i < n; i += gridDim.x * blockDim.x) {
        unsigned char m;
        if (mode == 2)      m = (((const unsigned char*)raw)[i] != 0);
        else if (mode == 1) m = (((const float*)raw)[i] != 0.0f);
        else                m = (((const unsigned int*)raw)[i] != 0u);
        g_mask[i] = m;
    }
}

// ============================================================
// GEMM 64x32 tile, 256 threads, 4x2 per thread, K-tile 16.
// Small tiles -> many blocks -> multiple blocks/SM.
// ============================================================
__device__ __forceinline__ void gemm_body(
    const float* __restrict__ A, const float* __restrict__ W,
    const float* __restrict__ bias, float* __restrict__ C,
    int M, int K, int Nc, int m0, int n0)
{
    __shared__ float As[16][65];
    __shared__ float Bs[16][33];
    const int t = threadIdx.x;
    const int r = t >> 4, c = t & 15;
    float acc[4][2] = {};

    for (int k0 = 0; k0 < K; k0 += 16) {
        #pragma unroll
        for (int l = 0; l < 4; l++) {
            int idx = t + l * 256;
            int mm = idx >> 4, kk = idx & 15;
            As[kk][mm] = A[(m0 + mm) * K + (k0 + kk)];
        }
        #pragma unroll
        for (int l = 0; l < 2; l++) {
            int idx = t + l * 256;
            int kk = idx >> 5, nn = idx & 31;
            Bs[kk][nn] = W[(k0 + kk) * Nc + (n0 + nn)];
        }
        __syncthreads();
        #pragma unroll
        for (int kk = 0; kk < 16; kk++) {
            float av[4], bv[2];
            #pragma unroll
            for (int l = 0; l < 4; l++) av[l] = As[kk][r * 4 + l];
            bv[0] = Bs[kk][c * 2];
            bv[1] = Bs[kk][c * 2 + 1];
            #pragma unroll
            for (int i = 0; i < 4; i++) {
                acc[i][0] += av[i] * bv[0];
                acc[i][1] += av[i] * bv[1];
            }
        }
        __syncthreads();
    }

    #pragma unroll
    for (int i = 0; i < 4; i++)
        #pragma unroll
        for (int j = 0; j < 2; j++) {
            int m = m0 + r * 4 + i, n = n0 + c * 2 + j;
            float v = acc[i][j];
            if (bias) v += bias[n];
            C[m * Nc + n] = v;
        }
}

// fused q/k/v projection: gridDim.x = 3*8 (weight sel x n-tiles), gridDim.y = M/64
__global__ __launch_bounds__(256) void qkv_gemm(
    const float* __restrict__ x,
    const float* __restrict__ Wq, const float* __restrict__ Wk, const float* __restrict__ Wv)
{
    const int sel = blockIdx.x >> 3;
    const int n0 = (blockIdx.x & 7) * 32;
    const int m0 = blockIdx.y * 64;
    const float* W = (sel == 0) ? Wq : (sel == 1) ? Wk : Wv;
    float* C = (sel == 0) ? g_q : (sel == 1) ? g_k : g_v;
    gemm_body(x, W, nullptr, C, BB * NN, QDIM, DIN, m0, n0);
}

__global__ __launch_bounds__(256) void gemm_tiled(
    const float* __restrict__ A, const float* __restrict__ W,
    const float* __restrict__ bias, float* __restrict__ C,
    int M, int K, int Nc)
{
    gemm_body(A, W, bias, C, M, K, Nc, blockIdx.y * 64, blockIdx.x * 32);
}

// ============================================================
// Fused attention: per block (b, 8 query rows), 512 threads.
// Two warps per query row, splitting the 256 MLP channels
// (ch = warp&1 -> channels [ch*128, ch*128+128)).
// ============================================================
__global__ __launch_bounds__(512, 1) void attn_fused(
    const float* __restrict__ edge_attr,
    const unsigned char* __restrict__ mask,
    const float* __restrict__ Web1, const float* __restrict__ beb1,
    const float* __restrict__ Web2, const float* __restrict__ beb2,
    const float* __restrict__ Wev1, const float* __restrict__ bev1,
    const float* __restrict__ Wev2, const float* __restrict__ bev2,
    float* __restrict__ attn_out)
{
    extern __shared__ float sm[];
    float* qs   = sm;                  // 2048
    float* S    = sm + 2048;           // 16384  (8 rows * 4 heads * 512)
    float* tsh  = sm + 18432;          // 8192
    float* vacc = sm + 26624;          // 2048
    float* esh  = sm + 28672;          // 2816
    float* kvs  = sm + 31488;          // 8192
    float* S2t  = sm + 39680;          // 1024   (ch1 partial scores for one j-tile)
    // total 40704 floats = 162816 bytes

    const int t = threadIdx.x;
    const int warp = t >> 5, lane = t & 31;
    const int b = blockIdx.y;
    const int i0 = blockIdx.x * ITILE;
    const int ii = warp >> 1;   // query row in tile (0..7)
    const int ch = warp & 1;    // channel half

    // ---- stage q rows (2048 floats contiguous) ----
    {
        const float4* src = (const float4*)&g_q[(b * NN + i0) * DIN];
        ((float4*)qs)[t] = src[t];
    }

    // ---- per-lane weight registers: 4 channel groups per lane ----
    float W1r[EDIM][4], b1r[4], W2r[4][4];
    #pragma unroll
    for (int c4 = 0; c4 < 4; c4++) {
        int cc = ch * 128 + lane + 32 * c4;
        b1r[c4] = beb1[cc];
        #pragma unroll
        for (int a = 0; a < EDIM; a++) W1r[a][c4] = Web1[a * DIN + cc];
        #pragma unroll
        for (int h = 0; h < NH; h++) W2r[c4][h] = Web2[cc * NH + h];
    }
    const float b2r0 = beb2[0], b2r1 = beb2[1], b2r2 = beb2[2], b2r3 = beb2[3];
    __syncthreads();

    // =================== PASS 1: sim + edge bias ===================
    for (int jt = 0; jt < NN; jt += JTILE) {
        {
            const float4* src = (const float4*)&g_k[(b * NN + jt) * DIN];
            float4* dst = (float4*)kvs;
            #pragma unroll
            for (int l = 0; l < 4; l++) dst[t + l * 512] = src[t + l * 512];
        }
        for (int idx = t; idx < ITILE * JTILE * EDIM; idx += 512) {
            int e_ii = idx / (JTILE * EDIM);
            int rem  = idx - e_ii * (JTILE * EDIM);
            esh[idx] = edge_attr[((size_t)(b * NN + i0 + e_ii) * NN + jt) * EDIM + rem];
        }
        __syncthreads();

        for (int jj = 0; jj < JTILE; jj++) {
            const int j = jt + jj;
            const unsigned char mk = mask[(b * NN + i0 + ii) * NN + j];
            if (!mk) {
                if (lane < NH) {
                    if (ch == 0) S[(ii * NH + lane) * NN + j] = NEGMAX;
                    else         S2t[(ii * NH + lane) * JTILE + jj] = 0.f;
                }
                continue;
            }
            float e[EDIM];
            #pragma unroll
            for (int a = 0; a < EDIM; a++) e[a] = esh[(ii * JTILE + jj) * EDIM + a];

            float red0, red1, red2, red3;
            if (ch == 0) {
                const float* kr = kvs + jj * DIN;
                const float* qr = qs + ii * DIN;
                red0 = SCALE_F * (qr[lane] * kr[lane] + qr[lane + 32] * kr[lane + 32]);
                red1 = SCALE_F * (qr[64 + lane] * kr[64 + lane] + qr[96 + lane] * kr[96 + lane]);
                red2 = SCALE_F * (qr[128 + lane] * kr[128 + lane] + qr[160 + lane] * kr[160 + lane]);
                red3 = SCALE_F * (qr[192 + lane] * kr[192 + lane] + qr[224 + lane] * kr[224 + lane]);
            } else {
                red0 = red1 = red2 = red3 = 0.f;
            }

            #pragma unroll
            for (int c4 = 0; c4 < 4; c4++) {
                float s = b1r[c4];
                #pragma unroll
                for (int a = 0; a < EDIM; a++) s += e[a] * W1r[a][c4];
                float g = gelu_exact(s);
                red0 += g * W2r[c4][0];
                red1 += g * W2r[c4][1];
                red2 += g * W2r[c4][2];
                red3 += g * W2r[c4][3];
            }
            #pragma unroll
            for (int off = 16; off > 0; off >>= 1) {
                red0 += __shfl_xor_sync(0xffffffffu, red0, off);
                red1 += __shfl_xor_sync(0xffffffffu, red1, off);
                red2 += __shfl_xor_sync(0xffffffffu, red2, off);
                red3 += __shfl_xor_sync(0xffffffffu, red3, off);
            }
            if (lane < 4) {
                float v = (lane == 0) ? red0 : (lane == 1) ? red1 : (lane == 2) ? red2 : red3;
                if (ch == 0) {
                    float bb = (lane == 0) ? b2r0 : (lane == 1) ? b2r1 : (lane == 2) ? b2r2 : b2r3;
                    S[(ii * NH + lane) * NN + j] = v + bb;
                } else {
                    S2t[(ii * NH + lane) * JTILE + jj] = v;
                }
            }
        }
        __syncthreads();
        // combine ch1 partials into S (deterministic, no atomics)
        for (int idx = t; idx < ITILE * NH * JTILE; idx += 512) {
            int r = idx >> 5, jj = idx & 31;
            S[r * NN + jt + jj] += S2t[idx];
        }
        __syncthreads();
    }

    // =================== PASS 2: softmax (16 warps x 2 rows) ===================
    #pragma unroll
    for (int rr = 0; rr < 2; rr++) {
        const int row = warp * 2 + rr;       // 0..31  == rii*4 + h
        const int rii = row >> 2, h = row & 3;
        float vals[16];
        float m = NEGMAX;
        #pragma unroll
        for (int kk = 0; kk < 16; kk++) {
            vals[kk] = S[row * NN + lane + kk * 32];
            m = fmaxf(m, vals[kk]);
        }
        #pragma unroll
        for (int off = 16; off > 0; off >>= 1)
            m = fmaxf(m, __shfl_xor_sync(0xffffffffu, m, off));
        float sum = 0.f;
        #pragma unroll
        for (int kk = 0; kk < 16; kk++) {
            float p = __expf(vals[kk] - m);
            vals[kk] = p;
            sum += p;
        }
        #pragma unroll
        for (int off = 16; off > 0; off >>= 1)
            sum += __shfl_xor_sync(0xffffffffu, sum, off);
        const float inv = 1.0f / sum;
        float* arow = attn_out + (((size_t)b * NH + h) * NN + (i0 + rii)) * NN;
        #pragma unroll
        for (int kk = 0; kk < 16; kk++) {
            float a = vals[kk] * inv;
            S[row * NN + lane + kk * 32] = a;
            arow[lane + kk * 32] = a;
        }
    }
    __syncthreads();

    // =================== PASS 3: t and attn@v accumulation ===================
    #pragma unroll
    for (int c4 = 0; c4 < 4; c4++) {
        int cc = ch * 128 + lane + 32 * c4;
        b1r[c4] = bev1[cc];
        #pragma unroll
        for (int a = 0; a < EDIM; a++) W1r[a][c4] = Wev1[a * DIN + cc];
    }
    float tr[NH][4] = {};     // [head][channel group]
    float va[2][2] = {};      // this warp's 2 heads (ch*2+hh), 2 dim-chunks

    for (int jt = 0; jt < NN; jt += JTILE) {
        {
            const float4* src = (const float4*)&g_v[(b * NN + jt) * DIN];
            float4* dst = (float4*)kvs;
            #pragma unroll
            for (int l = 0; l < 4; l++) dst[t + l * 512] = src[t + l * 512];
        }
        for (int idx = t; idx < ITILE * JTILE * EDIM; idx += 512) {
            int e_ii = idx / (JTILE * EDIM);
            int rem  = idx - e_ii * (JTILE * EDIM);
            esh[idx] = edge_attr[((size_t)(b * NN + i0 + e_ii) * NN + jt) * EDIM + rem];
        }
        __syncthreads();

        for (int jj = 0; jj < JTILE; jj++) {
            const int j = jt + jj;
            float a4[4];
            #pragma unroll
            for (int h = 0; h < NH; h++) a4[h] = S[(ii * NH + h) * NN + j];
            if (a4[0] + a4[1] + a4[2] + a4[3] == 0.f) continue;  // masked: exact zeros

            float e[EDIM];
            #pragma unroll
            for (int a = 0; a < EDIM; a++) e[a] = esh[(ii * JTILE + jj) * EDIM + a];

            #pragma unroll
            for (int c4 = 0; c4 < 4; c4++) {
                float s = b1r[c4];
                #pragma unroll
                for (int a = 0; a < EDIM; a++) s += e[a] * W1r[a][c4];
                float g = gelu_exact(s);
                #pragma unroll
                for (int h = 0; h < NH; h++) tr[h][c4] += a4[h] * g;
            }
            const float* vr = kvs + jj * DIN;
            #pragma unroll
            for (int hh = 0; hh < 2; hh++) {
                const int h = ch * 2 + hh;
                va[hh][0] += a4[h] * vr[h * 64 + lane];
                va[hh][1] += a4[h] * vr[h * 64 + lane + 32];
            }
        }
        __syncthreads();
    }

    // dump accumulators to shared (disjoint regions per channel half / head pair)
    #pragma unroll
    for (int h = 0; h < NH; h++)
        #pragma unroll
        for (int c4 = 0; c4 < 4; c4++)
            tsh[(ii * NH + h) * DIN + ch * 128 + lane + 32 * c4] = tr[h][c4];
    #pragma unroll
    for (int hh = 0; hh < 2; hh++) {
        const int h = ch * 2 + hh;
        vacc[ii * DIN + h * 64 + lane]      = va[hh][0];
        vacc[ii * DIN + h * 64 + lane + 32] = va[hh][1];
    }
    __syncthreads();

    // =================== FINAL: o_inner = vacc + t@Wev2 + bev2 ===================
    {
        const int col = t & 255;
        const int part = t >> 8;            // 0 or 1 -> rows 0..3 / 4..7
        const int h = col >> 6;
        const float bcol = bev2[col];
        for (int i2 = part * 4; i2 < part * 4 + 4; i2++) {
            const float* trow = &tsh[(i2 * NH + h) * DIN];
            float acc0 = 0.f, acc1 = 0.f, acc2 = 0.f, acc3 = 0.f;
            #pragma unroll 4
            for (int cc = 0; cc < DIN; cc += 4) {
                acc0 += trow[cc]     * Wev2[(cc)     * DIN + col];
                acc1 += trow[cc + 1] * Wev2[(cc + 1) * DIN + col];
                acc2 += trow[cc + 2] * Wev2[(cc + 2) * DIN + col];
                acc3 += trow[cc + 3] * Wev2[(cc + 3) * DIN + col];
            }
            g_oi[(b * NN + i0 + i2) * DIN + col] =
                ((acc0 + acc1) + (acc2 + acc3)) + vacc[i2 * DIN + col] + bcol;
        }
    }
}

// ============================================================
extern "C" void kernel_launch(void* const* d_in, const int* in_sizes, int n_in,
                              void* d_out, int out_size)
{
    const float* x           = (const float*)d_in[0];
    const void*  mask_raw    = d_in[1];
    const float* ea          = (const float*)d_in[2];
    const float* Wq          = (const float*)d_in[3];
    const float* Wk          = (const float*)d_in[4];
    const float* Wv          = (const float*)d_in[5];
    const float* Web1        = (const float*)d_in[6];
    const float* beb1        = (const float*)d_in[7];
    const float* Web2        = (const float*)d_in[8];
    const float* beb2        = (const float*)d_in[9];
    const float* Wev1        = (const float*)d_in[10];
    const float* bev1        = (const float*)d_in[11];
    const float* Wev2        = (const float*)d_in[12];
    const float* bev2        = (const float*)d_in[13];
    const float* Wo          = (const float*)d_in[14];
    const float* bo          = (const float*)d_in[15];

    float* out = (float*)d_out;
    const int out_elems  = BB * NN * QDIM;              // 524288
    const int attn_elems = BB * NH * NN * NN;           // 2097152
    const int mask_elems = BB * NN * NN;                // 524288

    float *oip, *attn_fb;
    unsigned char* maskp;
    cudaGetSymbolAddress((void**)&oip, g_oi);
    cudaGetSymbolAddress((void**)&attn_fb, g_attn_scratch);
    cudaGetSymbolAddress((void**)&maskp, g_mask);

    float* attn = (out_size >= out_elems + attn_elems) ? (out + out_elems) : attn_fb;

    const int smem_bytes = 40704 * 4;
    cudaFuncSetAttribute(attn_fused, cudaFuncAttributeMaxDynamicSharedMemorySize, smem_bytes);

    // mask dtype sniff + canonicalize to uint8
    detect_mask_kernel<<<1, 256>>>((const unsigned int*)mask_raw, mask_elems / 4);
    canon_mask_kernel<<<256, 256>>>(mask_raw, mask_elems);

    // fused q/k/v projections: 3 weights x 8 n-tiles x 16 m-tiles = 384 blocks
    qkv_gemm<<<dim3(24, (BB * NN) / 64), 256>>>(x, Wq, Wk, Wv);

    // fused attention + edge MLPs (512 threads, 2 warps per query row)
    attn_fused<<<dim3(NN / ITILE, BB), 512, smem_bytes>>>(
        ea, maskp, Web1, beb1, Web2, beb2, Wev1, bev1, Wev2, bev2, attn);

    // final projection: out = o_inner @ Wo + bo   (16 x 16 = 256 blocks)
    gemm_tiled<<<dim3(QDIM / 32, (BB * NN) / 64), 256>>>(oip, Wo, bo, out, BB * NN, DIN, QDIM);
}

// round 6
// speedup vs baseline: 2.0166x; 1.2683x over previous
#include <cuda_runtime.h>
#include <math.h>

#define BB 2
#define NN 512
#define QDIM 512
#define EDIM 11
#define NH 4
#define DHEAD 64
#define DIN 256          // INNER = NH*DHEAD
#define SCALE_F 0.125f   // 64^-0.5
#define NEGMAX -3.402823466e38f

#define ITILE 4
#define JTILE 32
#define ESTRIDE 12       // padded edge-feature row stride (16B-aligned float4 loads)

// -------- device scratch (no allocations allowed) --------
__device__ float g_q[BB * NN * DIN];
__device__ float g_k[BB * NN * DIN];
__device__ float g_v[BB * NN * DIN];
__device__ float g_oi[BB * NN * DIN];
__device__ float g_attn_scratch[BB * NH * NN * NN];
__device__ unsigned char g_mask[BB * NN * NN];
__device__ int g_mask_mode;   // 0 = int32, 1 = float32, 2 = uint8/bool

// fast GELU: 0.5x(1+tanh(0.79788456(x+0.044715x^3))); tanh.approx is 1 HW inst.
// For this problem's tiny pre-activations (|x| < ~0.5) abs error vs exact-erf
// GELU is ~1e-5, invisible at the 1e-3 rel-err threshold.
__device__ __forceinline__ float gelu_fast(float x) {
    float x3 = x * x * x;
    float u = 0.7978845608f * fmaf(0.044715f, x3, x);
    float th;
    asm("tanh.approx.f32 %0, %1;" : "=f"(th) : "f"(u));
    return 0.5f * x * (1.0f + th);
}

// ============================================================
// Mask dtype sniffing + canonicalization (proven in round 4).
// ============================================================
__global__ void detect_mask_kernel(const unsigned int* __restrict__ w, int nwords) {
    __shared__ int s_weird, s_float;
    if (threadIdx.x == 0) { s_weird = 0; s_float = 0; }
    __syncthreads();
    int weird = 0, flt = 0;
    for (int i = threadIdx.x; i < nwords; i += blockDim.x) {
        unsigned int v = w[i];
        if (v == 0x3F800000u) flt = 1;
        else if (v > 1u) weird = 1;
    }
    if (weird) atomicOr(&s_weird, 1);
    if (flt)   atomicOr(&s_float, 1);
    __syncthreads();
    if (threadIdx.x == 0)
        g_mask_mode = s_weird ? 2 : (s_float ? 1 : 0);
}

__global__ void canon_mask_kernel(const void* __restrict__ raw, int n) {
    const int mode = g_mask_mode;
    for (int i = blockIdx.x * blockDim.x + threadIdx.x; i < n; i += gridDim.x * blockDim.x) {
        unsigned char m;
        if (mode == 2)      m = (((const unsigned char*)raw)[i] != 0);
        else if (mode == 1) m = (((const float*)raw)[i] != 0.0f);
        else                m = (((const unsigned int*)raw)[i] != 0u);
        g_mask[i] = m;
    }
}

// ============================================================
// GEMM 64x32 tile, 256 threads, 4x2 per thread, K-tile 16.
// ============================================================
__device__ __forceinline__ void gemm_body(
    const float* __restrict__ A, const float* __restrict__ W,
    const float* __restrict__ bias, float* __restrict__ C,
    int M, int K, int Nc, int m0, int n0)
{
    __shared__ float As[16][65];
    __shared__ float Bs[16][33];
    const int t = threadIdx.x;
    const int r = t >> 4, c = t & 15;
    float acc[4][2] = {};

    for (int k0 = 0; k0 < K; k0 += 16) {
        #pragma unroll
        for (int l = 0; l < 4; l++) {
            int idx = t + l * 256;
            int mm = idx >> 4, kk = idx & 15;
            As[kk][mm] = A[(m0 + mm) * K + (k0 + kk)];
        }
        #pragma unroll
        for (int l = 0; l < 2; l++) {
            int idx = t + l * 256;
            int kk = idx >> 5, nn = idx & 31;
            Bs[kk][nn] = W[(k0 + kk) * Nc + (n0 + nn)];
        }
        __syncthreads();
        #pragma unroll
        for (int kk = 0; kk < 16; kk++) {
            float av[4], bv[2];
            #pragma unroll
            for (int l = 0; l < 4; l++) av[l] = As[kk][r * 4 + l];
            bv[0] = Bs[kk][c * 2];
            bv[1] = Bs[kk][c * 2 + 1];
            #pragma unroll
            for (int i = 0; i < 4; i++) {
                acc[i][0] += av[i] * bv[0];
                acc[i][1] += av[i] * bv[1];
            }
        }
        __syncthreads();
    }

    #pragma unroll
    for (int i = 0; i < 4; i++)
        #pragma unroll
        for (int j = 0; j < 2; j++) {
            int m = m0 + r * 4 + i, n = n0 + c * 2 + j;
            float v = acc[i][j];
            if (bias) v += bias[n];
            C[m * Nc + n] = v;
        }
}

__global__ __launch_bounds__(256) void qkv_gemm(
    const float* __restrict__ x,
    const float* __restrict__ Wq, const float* __restrict__ Wk, const float* __restrict__ Wv)
{
    const int sel = blockIdx.x >> 3;
    const int n0 = (blockIdx.x & 7) * 32;
    const int m0 = blockIdx.y * 64;
    const float* W = (sel == 0) ? Wq : (sel == 1) ? Wk : Wv;
    float* C = (sel == 0) ? g_q : (sel == 1) ? g_k : g_v;
    gemm_body(x, W, nullptr, C, BB * NN, QDIM, DIN, m0, n0);
}

__global__ __launch_bounds__(256) void gemm_tiled(
    const float* __restrict__ A, const float* __restrict__ W,
    const float* __restrict__ bias, float* __restrict__ C,
    int M, int K, int Nc)
{
    gemm_body(A, W, bias, C, M, K, Nc, blockIdx.y * 64, blockIdx.x * 32);
}

// ============================================================
// Fused attention: per block (b, 4 query rows), 256 threads,
// 2 blocks/SM. Two warps per query row split the 256 MLP channels.
// ============================================================
__global__ __launch_bounds__(256, 2) void attn_fused(
    const float* __restrict__ edge_attr,
    const unsigned char* __restrict__ mask,
    const float* __restrict__ Web1, const float* __restrict__ beb1,
    const float* __restrict__ Web2, const float* __restrict__ beb2,
    const float* __restrict__ Wev1, const float* __restrict__ bev1,
    const float* __restrict__ Wev2, const float* __restrict__ bev2,
    float* __restrict__ attn_out)
{
    extern __shared__ float sm[];
    float* qs   = sm;                  // 1024   (4*256)
    float* S    = sm + 1024;           // 8192   (4 rows * 4 heads * 512)
    float* tsh  = sm + 9216;           // 4096   (4*4*256)
    float* vacc = sm + 13312;          // 1024
    float* esh  = sm + 14336;          // 1536   (4*32*ESTRIDE)
    float* kvs  = sm + 15872;          // 8192   (32*256)
    float* S2t  = sm + 24064;          // 512    (4*4*32)
    unsigned char* msh = (unsigned char*)(sm + 24576);  // 2048 bytes (4*512)
    // total 25088 floats = 100352 bytes

    const int t = threadIdx.x;
    const int warp = t >> 5, lane = t & 31;
    const int b = blockIdx.y;
    const int i0 = blockIdx.x * ITILE;
    const int ii = warp >> 1;   // query row in tile (0..3)
    const int ch = warp & 1;    // channel half
    const int hsel = lane >> 3; // head this lane finalizes in the reduction
    const int lead = ((lane & 7) == 0);

    // ---- stage q rows (1024 floats) + mask rows (2048 bytes) ----
    ((float4*)qs)[t] = ((const float4*)&g_q[(b * NN + i0) * DIN])[t];
    {
        const unsigned int* msrc = (const unsigned int*)&mask[(b * NN + i0) * NN];
        unsigned int* mdst = (unsigned int*)msh;
        mdst[t] = msrc[t];
        mdst[t + 256] = msrc[t + 256];
    }

    // ---- per-lane weight registers: 4 channel groups per lane ----
    float W1r[EDIM][4], b1r[4], W2r[4][4];
    #pragma unroll
    for (int c4 = 0; c4 < 4; c4++) {
        int cc = ch * 128 + lane + 32 * c4;
        b1r[c4] = beb1[cc];
        #pragma unroll
        for (int a = 0; a < EDIM; a++) W1r[a][c4] = Web1[a * DIN + cc];
        #pragma unroll
        for (int h = 0; h < NH; h++) W2r[c4][h] = Web2[cc * NH + h];
    }
    const float b2h = beb2[hsel];   // bias for the head this lane writes
    __syncthreads();

    // =================== PASS 1: sim + edge bias ===================
    for (int jt = 0; jt < NN; jt += JTILE) {
        {
            const float4* src = (const float4*)&g_k[(b * NN + jt) * DIN];
            float4* dst = (float4*)kvs;
            #pragma unroll
            for (int l = 0; l < 8; l++) dst[t + l * 256] = src[t + l * 256];
        }
        for (int idx = t; idx < ITILE * JTILE * EDIM; idx += 256) {
            int r = idx / EDIM, a = idx - r * EDIM;
            int e_ii = r >> 5, jj = r & 31;
            esh[r * ESTRIDE + a] =
                edge_attr[((size_t)(b * NN + i0 + e_ii) * NN + jt + jj) * EDIM + a];
        }
        __syncthreads();

        for (int jj = 0; jj < JTILE; jj++) {
            const int j = jt + jj;
            if (!msh[ii * NN + j]) {
                if (lead) {
                    if (ch == 0) S[(ii * NH + hsel) * NN + j] = NEGMAX;
                    else         S2t[(ii * NH + hsel) * JTILE + jj] = 0.f;
                }
                continue;
            }
            const float* er = esh + (ii * JTILE + jj) * ESTRIDE;
            float4 e0 = *(const float4*)er;
            float4 e1 = *(const float4*)(er + 4);
            float4 e2 = *(const float4*)(er + 8);
            float e[EDIM] = {e0.x, e0.y, e0.z, e0.w, e1.x, e1.y, e1.z, e1.w,
                             e2.x, e2.y, e2.z};

            float red0, red1, red2, red3;
            if (ch == 0) {
                const float* kr = kvs + jj * DIN;
                const float* qr = qs + ii * DIN;
                red0 = SCALE_F * (qr[lane] * kr[lane] + qr[lane + 32] * kr[lane + 32]);
                red1 = SCALE_F * (qr[64 + lane] * kr[64 + lane] + qr[96 + lane] * kr[96 + lane]);
                red2 = SCALE_F * (qr[128 + lane] * kr[128 + lane] + qr[160 + lane] * kr[160 + lane]);
                red3 = SCALE_F * (qr[192 + lane] * kr[192 + lane] + qr[224 + lane] * kr[224 + lane]);
            } else {
                red0 = red1 = red2 = red3 = 0.f;
            }

            #pragma unroll
            for (int c4 = 0; c4 < 4; c4++) {
                float s = b1r[c4];
                #pragma unroll
                for (int a = 0; a < EDIM; a++) s += e[a] * W1r[a][c4];
                float g = gelu_fast(s);
                red0 += g * W2r[c4][0];
                red1 += g * W2r[c4][1];
                red2 += g * W2r[c4][2];
                red3 += g * W2r[c4][3];
            }
            // 2 butterfly rounds on all four, redistribute, 3 rounds on one
            #pragma unroll
            for (int off = 16; off >= 8; off >>= 1) {
                red0 += __shfl_xor_sync(0xffffffffu, red0, off);
                red1 += __shfl_xor_sync(0xffffffffu, red1, off);
                red2 += __shfl_xor_sync(0xffffffffu, red2, off);
                red3 += __shfl_xor_sync(0xffffffffu, red3, off);
            }
            float w = (hsel == 0) ? red0 : (hsel == 1) ? red1 : (hsel == 2) ? red2 : red3;
            w += __shfl_xor_sync(0xffffffffu, w, 4);
            w += __shfl_xor_sync(0xffffffffu, w, 2);
            w += __shfl_xor_sync(0xffffffffu, w, 1);
            if (lead) {
                if (ch == 0) S[(ii * NH + hsel) * NN + j] = w + b2h;
                else         S2t[(ii * NH + hsel) * JTILE + jj] = w;
            }
        }
        __syncthreads();
        // combine ch1 partials into S (deterministic)
        for (int idx = t; idx < ITILE * NH * JTILE; idx += 256) {
            int r = idx >> 5, jj = idx & 31;
            S[r * NN + jt + jj] += S2t[idx];
        }
        __syncthreads();
    }

    // =================== PASS 2: softmax (8 warps x 2 rows) ===================
    #pragma unroll
    for (int rr = 0; rr < 2; rr++) {
        const int row = warp * 2 + rr;       // 0..15  == rii*4 + h
        const int rii = row >> 2, h = row & 3;
        float vals[16];
        float m = NEGMAX;
        #pragma unroll
        for (int kk = 0; kk < 16; kk++) {
            vals[kk] = S[row * NN + lane + kk * 32];
            m = fmaxf(m, vals[kk]);
        }
        #pragma unroll
        for (int off = 16; off > 0; off >>= 1)
            m = fmaxf(m, __shfl_xor_sync(0xffffffffu, m, off));
        float sum = 0.f;
        #pragma unroll
        for (int kk = 0; kk < 16; kk++) {
            float p = __expf(vals[kk] - m);
            vals[kk] = p;
            sum += p;
        }
        #pragma unroll
        for (int off = 16; off > 0; off >>= 1)
            sum += __shfl_xor_sync(0xffffffffu, sum, off);
        const float inv = 1.0f / sum;
        float* arow = attn_out + (((size_t)b * NH + h) * NN + (i0 + rii)) * NN;
        #pragma unroll
        for (int kk = 0; kk < 16; kk++) {
            float a = vals[kk] * inv;
            S[row * NN + lane + kk * 32] = a;
            arow[lane + kk * 32] = a;
        }
    }
    __syncthreads();

    // =================== PASS 3: t and attn@v accumulation ===================
    #pragma unroll
    for (int c4 = 0; c4 < 4; c4++) {
        int cc = ch * 128 + lane + 32 * c4;
        b1r[c4] = bev1[cc];
        #pragma unroll
        for (int a = 0; a < EDIM; a++) W1r[a][c4] = Wev1[a * DIN + cc];
    }
    float tr[NH][4] = {};
    float va[2][2] = {};

    for (int jt = 0; jt < NN; jt += JTILE) {
        {
            const float4* src = (const float4*)&g_v[(b * NN + jt) * DIN];
            float4* dst = (float4*)kvs;
            #pragma unroll
            for (int l = 0; l < 8; l++) dst[t + l * 256] = src[t + l * 256];
        }
        for (int idx = t; idx < ITILE * JTILE * EDIM; idx += 256) {
            int r = idx / EDIM, a = idx - r * EDIM;
            int e_ii = r >> 5, jj = r & 31;
            esh[r * ESTRIDE + a] =
                edge_attr[((size_t)(b * NN + i0 + e_ii) * NN + jt + jj) * EDIM + a];
        }
        __syncthreads();

        for (int jj = 0; jj < JTILE; jj++) {
            const int j = jt + jj;
            float a4[4];
            #pragma unroll
            for (int h = 0; h < NH; h++) a4[h] = S[(ii * NH + h) * NN + j];
            if (a4[0] + a4[1] + a4[2] + a4[3] == 0.f) continue;  // masked: exact zeros

            const float* er = esh + (ii * JTILE + jj) * ESTRIDE;
            float4 e0 = *(const float4*)er;
            float4 e1 = *(const float4*)(er + 4);
            float4 e2 = *(const float4*)(er + 8);
            float e[EDIM] = {e0.x, e0.y, e0.z, e0.w, e1.x, e1.y, e1.z, e1.w,
                             e2.x, e2.y, e2.z};

            #pragma unroll
            for (int c4 = 0; c4 < 4; c4++) {
                float s = b1r[c4];
                #pragma unroll
                for (int a = 0; a < EDIM; a++) s += e[a] * W1r[a][c4];
                float g = gelu_fast(s);
                #pragma unroll
                for (int h = 0; h < NH; h++) tr[h][c4] += a4[h] * g;
            }
            const float* vr = kvs + jj * DIN;
            #pragma unroll
            for (int hh = 0; hh < 2; hh++) {
                const int h = ch * 2 + hh;
                va[hh][0] += a4[h] * vr[h * 64 + lane];
                va[hh][1] += a4[h] * vr[h * 64 + lane + 32];
            }
        }
        __syncthreads();
    }

    // dump accumulators to shared (disjoint regions)
    #pragma unroll
    for (int h = 0; h < NH; h++)
        #pragma unroll
        for (int c4 = 0; c4 < 4; c4++)
            tsh[(ii * NH + h) * DIN + ch * 128 + lane + 32 * c4] = tr[h][c4];
    #pragma unroll
    for (int hh = 0; hh < 2; hh++) {
        const int h = ch * 2 + hh;
        vacc[ii * DIN + h * 64 + lane]      = va[hh][0];
        vacc[ii * DIN + h * 64 + lane + 32] = va[hh][1];
    }
    __syncthreads();

    // =================== FINAL: o_inner = vacc + t@Wev2 + bev2 ===================
    {
        const int col = t;
        const int h = col >> 6;
        const float bcol = bev2[col];
        for (int i2 = 0; i2 < ITILE; i2++) {
            const float* trow = &tsh[(i2 * NH + h) * DIN];
            float acc0 = 0.f, acc1 = 0.f, acc2 = 0.f, acc3 = 0.f;
            #pragma unroll 4
            for (int cc = 0; cc < DIN; cc += 4) {
                acc0 += trow[cc]     * Wev2[(cc)     * DIN + col];
                acc1 += trow[cc + 1] * Wev2[(cc + 1) * DIN + col];
                acc2 += trow[cc + 2] * Wev2[(cc + 2) * DIN + col];
                acc3 += trow[cc + 3] * Wev2[(cc + 3) * DIN + col];
            }
            g_oi[(b * NN + i0 + i2) * DIN + col] =
                ((acc0 + acc1) + (acc2 + acc3)) + vacc[i2 * DIN + col] + bcol;
        }
    }
}

// ============================================================
extern "C" void kernel_launch(void* const* d_in, const int* in_sizes, int n_in,
                              void* d_out, int out_size)
{
    const float* x           = (const float*)d_in[0];
    const void*  mask_raw    = d_in[1];
    const float* ea          = (const float*)d_in[2];
    const float* Wq          = (const float*)d_in[3];
    const float* Wk          = (const float*)d_in[4];
    const float* Wv          = (const float*)d_in[5];
    const float* Web1        = (const float*)d_in[6];
    const float* beb1        = (const float*)d_in[7];
    const float* Web2        = (const float*)d_in[8];
    const float* beb2        = (const float*)d_in[9];
    const float* Wev1        = (const float*)d_in[10];
    const float* bev1        = (const float*)d_in[11];
    const float* Wev2        = (const float*)d_in[12];
    const float* bev2        = (const float*)d_in[13];
    const float* Wo          = (const float*)d_in[14];
    const float* bo          = (const float*)d_in[15];

    float* out = (float*)d_out;
    const int out_elems  = BB * NN * QDIM;              // 524288
    const int attn_elems = BB * NH * NN * NN;           // 2097152
    const int mask_elems = BB * NN * NN;                // 524288

    float *oip, *attn_fb;
    unsigned char* maskp;
    cudaGetSymbolAddress((void**)&oip, g_oi);
    cudaGetSymbolAddress((void**)&attn_fb, g_attn_scratch);
    cudaGetSymbolAddress((void**)&maskp, g_mask);

    float* attn = (out_size >= out_elems + attn_elems) ? (out + out_elems) : attn_fb;

    const int smem_bytes = 25088 * 4;   // 100352
    cudaFuncSetAttribute(attn_fused, cudaFuncAttributeMaxDynamicSharedMemorySize, smem_bytes);

    // mask dtype sniff + canonicalize to uint8
    detect_mask_kernel<<<1, 256>>>((const unsigned int*)mask_raw, mask_elems / 4);
    canon_mask_kernel<<<256, 256>>>(mask_raw, mask_elems);

    // fused q/k/v projections: 3 weights x 8 n-tiles x 16 m-tiles = 384 blocks
    qkv_gemm<<<dim3(24, (BB * NN) / 64), 256>>>(x, Wq, Wk, Wv);

    // fused attention + edge MLPs (256 threads, 2 blocks/SM, 256 blocks)
    attn_fused<<<dim3(NN / ITILE, BB), 256, smem_bytes>>>(
        ea, maskp, Web1, beb1, Web2, beb2, Wev1, bev1, Wev2, bev2, attn);

    // final projection: out = o_inner @ Wo + bo   (16 x 16 = 256 blocks)
    gemm_tiled<<<dim3(QDIM / 32, (BB * NN) / 64), 256>>>(oip, Wo, bo, out, BB * NN, DIN, QDIM);
}

// round 7
// speedup vs baseline: 2.0630x; 1.0230x over previous
#include <cuda_runtime.h>
#include <math.h>

#define BB 2
#define NN 512
#define QDIM 512
#define EDIM 11
#define NH 4
#define DHEAD 64
#define DIN 256          // INNER = NH*DHEAD
#define SCALE_F 0.125f   // 64^-0.5
#define NEGMAX -3.402823466e38f

#define ITILE 2
#define JTILE 16
#define ESTRIDE 12       // padded edge-feature row stride

// -------- device scratch (no allocations allowed) --------
__device__ float g_q[BB * NN * DIN];
__device__ float g_k[BB * NN * DIN];
__device__ float g_v[BB * NN * DIN];
__device__ float g_oi[BB * NN * DIN];
__device__ float g_attn_scratch[BB * NH * NN * NN];
__device__ unsigned char g_mask[BB * NN * NN];

// fast GELU via tanh.approx (validated R6: rel_err 4.7e-7 total)
__device__ __forceinline__ float gelu_fast(float x) {
    float x3 = x * x * x;
    float u = 0.7978845608f * fmaf(0.044715f, x3, x);
    float th;
    asm("tanh.approx.f32 %0, %1;" : "=f"(th) : "f"(u));
    return 0.5f * x * (1.0f + th);
}

// ============================================================
// Mask canonicalization with embedded dtype detection.
// Each block samples the first 4096 words (in-bounds for every
// candidate dtype; random bools make byte-storage unambiguous
// with probability 1-2^-1000), then converts its grid-stride slice.
// ============================================================
__global__ __launch_bounds__(256) void canon_mask_kernel(
    const unsigned int* __restrict__ raw, int n)
{
    int weird = 0, flt = 0;
    for (int i = threadIdx.x; i < 4096; i += 256) {
        unsigned int v = raw[i];
        if (v == 0x3F800000u) flt = 1;
        else if (v > 1u) weird = 1;
    }
    weird = __syncthreads_or(weird);
    flt   = __syncthreads_or(flt);
    const int mode = weird ? 2 : (flt ? 1 : 0);

    for (int i = blockIdx.x * blockDim.x + threadIdx.x; i < n; i += gridDim.x * blockDim.x) {
        unsigned char m;
        if (mode == 2)      m = (((const unsigned char*)raw)[i] != 0);
        else if (mode == 1) m = (((const float*)raw)[i] != 0.0f);
        else                m = (raw[i] != 0u);
        g_mask[i] = m;
    }
}

// ============================================================
// GEMM 64x32 tile, 256 threads, 4x2 per thread, K-tile 16.
// ============================================================
__device__ __forceinline__ void gemm_body(
    const float* __restrict__ A, const float* __restrict__ W,
    const float* __restrict__ bias, float* __restrict__ C,
    int M, int K, int Nc, int m0, int n0)
{
    __shared__ float As[16][65];
    __shared__ float Bs[16][33];
    const int t = threadIdx.x;
    const int r = t >> 4, c = t & 15;
    float acc[4][2] = {};

    for (int k0 = 0; k0 < K; k0 += 16) {
        #pragma unroll
        for (int l = 0; l < 4; l++) {
            int idx = t + l * 256;
            int mm = idx >> 4, kk = idx & 15;
            As[kk][mm] = A[(m0 + mm) * K + (k0 + kk)];
        }
        #pragma unroll
        for (int l = 0; l < 2; l++) {
            int idx = t + l * 256;
            int kk = idx >> 5, nn = idx & 31;
            Bs[kk][nn] = W[(k0 + kk) * Nc + (n0 + nn)];
        }
        __syncthreads();
        #pragma unroll
        for (int kk = 0; kk < 16; kk++) {
            float av[4], bv[2];
            #pragma unroll
            for (int l = 0; l < 4; l++) av[l] = As[kk][r * 4 + l];
            bv[0] = Bs[kk][c * 2];
            bv[1] = Bs[kk][c * 2 + 1];
            #pragma unroll
            for (int i = 0; i < 4; i++) {
                acc[i][0] += av[i] * bv[0];
                acc[i][1] += av[i] * bv[1];
            }
        }
        __syncthreads();
    }

    #pragma unroll
    for (int i = 0; i < 4; i++)
        #pragma unroll
        for (int j = 0; j < 2; j++) {
            int m = m0 + r * 4 + i, n = n0 + c * 2 + j;
            float v = acc[i][j];
            if (bias) v += bias[n];
            C[m * Nc + n] = v;
        }
}

__global__ __launch_bounds__(256) void qkv_gemm(
    const float* __restrict__ x,
    const float* __restrict__ Wq, const float* __restrict__ Wk, const float* __restrict__ Wv)
{
    const int sel = blockIdx.x >> 3;
    const int n0 = (blockIdx.x & 7) * 32;
    const int m0 = blockIdx.y * 64;
    const float* W = (sel == 0) ? Wq : (sel == 1) ? Wk : Wv;
    float* C = (sel == 0) ? g_q : (sel == 1) ? g_k : g_v;
    gemm_body(x, W, nullptr, C, BB * NN, QDIM, DIN, m0, n0);
}

__global__ __launch_bounds__(256) void gemm_tiled(
    const float* __restrict__ A, const float* __restrict__ W,
    const float* __restrict__ bias, float* __restrict__ C,
    int M, int K, int Nc)
{
    gemm_body(A, W, bias, C, M, K, Nc, blockIdx.y * 64, blockIdx.x * 32);
}

// ============================================================
// Fused attention: block = (b, 2 query rows), 256 threads,
// 4 blocks/SM. FOUR warps per query row, each owning a 64-channel
// quarter of the MLP hidden layer.
// smem layout (floats):
//   qs/vacc 0..512 | S 512..4608 | tsh 4608..6656 | esh 6656..7040
//   kvs 7040..11136 | S2t 11136..11520 | msh (bytes) 46080..47104
// total 47104 bytes -> 4 blocks/SM.
// ============================================================
__global__ __launch_bounds__(256, 4) void attn_fused(
    const float* __restrict__ edge_attr,
    const unsigned char* __restrict__ mask,
    const float* __restrict__ Web1, const float* __restrict__ beb1,
    const float* __restrict__ Web2, const float* __restrict__ beb2,
    const float* __restrict__ Wev1, const float* __restrict__ bev1,
    const float* __restrict__ Wev2, const float* __restrict__ bev2,
    float* __restrict__ attn_out)
{
    extern __shared__ float sm[];
    float* qs   = sm;                  // 512  (2*256), reused as vacc in pass 3
    float* vacc = sm;
    float* S    = sm + 512;            // 4096 (2 rows * 4 heads * 512)
    float* tsh  = sm + 4608;           // 2048 (2*4*256)
    float* esh  = sm + 6656;           // 384  (2*16*ESTRIDE)
    float* kvs  = sm + 7040;           // 4096 (16*256)
    float* S2t  = sm + 11136;          // 384  (3 partials * 2*4*16)
    unsigned char* msh = (unsigned char*)(sm + 11520);  // 1024 bytes

    const int t = threadIdx.x;
    const int warp = t >> 5, lane = t & 31;
    const int b = blockIdx.y;
    const int i0 = blockIdx.x * ITILE;
    const int ii = warp >> 2;    // query row in tile (0..1)
    const int qch = warp & 3;    // channel quarter (0..3)
    const int hsel = lane >> 3;  // head finalized by this lane
    const int lead = ((lane & 7) == 0);

    // ---- stage q rows (512 floats) + mask rows (1024 bytes) ----
    if (t < 128) ((float4*)qs)[t] = ((const float4*)&g_q[(b * NN + i0) * DIN])[t];
    ((unsigned int*)msh)[t] = ((const unsigned int*)&mask[(b * NN + i0) * NN])[t];

    // ---- per-lane weights: 2 channel groups (64 channels per warp) ----
    float W1r[EDIM][2], b1r[2], W2r[2][4];
    #pragma unroll
    for (int c2 = 0; c2 < 2; c2++) {
        int cc = qch * 64 + lane + 32 * c2;
        b1r[c2] = beb1[cc];
        #pragma unroll
        for (int a = 0; a < EDIM; a++) W1r[a][c2] = Web1[a * DIN + cc];
        #pragma unroll
        for (int h = 0; h < NH; h++) W2r[c2][h] = Web2[cc * NH + h];
    }
    const float b2h = beb2[hsel];
    __syncthreads();

    // hoist this row's q into registers (quarter 0 warps only)
    float qreg[NH][2];
    if (qch == 0) {
        #pragma unroll
        for (int h = 0; h < NH; h++) {
            qreg[h][0] = qs[ii * DIN + h * 64 + lane];
            qreg[h][1] = qs[ii * DIN + h * 64 + lane + 32];
        }
    }

    // =================== PASS 1: sim + edge bias ===================
    for (int jt = 0; jt < NN; jt += JTILE) {
        {
            const float4* src = (const float4*)&g_k[(b * NN + jt) * DIN];
            float4* dst = (float4*)kvs;
            #pragma unroll
            for (int l = 0; l < 4; l++) dst[t + l * 256] = src[t + l * 256];
        }
        if (t < ITILE * JTILE * EDIM - 256 || t < 256) {
            for (int idx = t; idx < ITILE * JTILE * EDIM; idx += 256) {
                int r = idx / EDIM, a = idx - r * EDIM;
                int e_ii = r >> 4, jj = r & 15;
                esh[r * ESTRIDE + a] =
                    edge_attr[((size_t)(b * NN + i0 + e_ii) * NN + jt + jj) * EDIM + a];
            }
        }
        __syncthreads();

        for (int jj = 0; jj < JTILE; jj++) {
            const int j = jt + jj;
            if (!msh[ii * NN + j]) {
                if (lead) {
                    if (qch == 0) S[(ii * NH + hsel) * NN + j] = NEGMAX;
                    else          S2t[(qch - 1) * 128 + (ii * NH + hsel) * JTILE + jj] = 0.f;
                }
                continue;
            }
            const float* er = esh + (ii * JTILE + jj) * ESTRIDE;
            float4 e0 = *(const float4*)er;
            float4 e1 = *(const float4*)(er + 4);
            float4 e2 = *(const float4*)(er + 8);
            float e[EDIM] = {e0.x, e0.y, e0.z, e0.w, e1.x, e1.y, e1.z, e1.w,
                             e2.x, e2.y, e2.z};

            float red0, red1, red2, red3;
            if (qch == 0) {
                const float* kr = kvs + jj * DIN;
                red0 = SCALE_F * (qreg[0][0] * kr[lane] + qreg[0][1] * kr[lane + 32]);
                red1 = SCALE_F * (qreg[1][0] * kr[64 + lane] + qreg[1][1] * kr[96 + lane]);
                red2 = SCALE_F * (qreg[2][0] * kr[128 + lane] + qreg[2][1] * kr[160 + lane]);
                red3 = SCALE_F * (qreg[3][0] * kr[192 + lane] + qreg[3][1] * kr[224 + lane]);
            } else {
                red0 = red1 = red2 = red3 = 0.f;
            }

            #pragma unroll
            for (int c2 = 0; c2 < 2; c2++) {
                float s = b1r[c2];
                #pragma unroll
                for (int a = 0; a < EDIM; a++) s += e[a] * W1r[a][c2];
                float g = gelu_fast(s);
                red0 += g * W2r[c2][0];
                red1 += g * W2r[c2][1];
                red2 += g * W2r[c2][2];
                red3 += g * W2r[c2][3];
            }
            #pragma unroll
            for (int off = 16; off >= 8; off >>= 1) {
                red0 += __shfl_xor_sync(0xffffffffu, red0, off);
                red1 += __shfl_xor_sync(0xffffffffu, red1, off);
                red2 += __shfl_xor_sync(0xffffffffu, red2, off);
                red3 += __shfl_xor_sync(0xffffffffu, red3, off);
            }
            float w = (hsel == 0) ? red0 : (hsel == 1) ? red1 : (hsel == 2) ? red2 : red3;
            w += __shfl_xor_sync(0xffffffffu, w, 4);
            w += __shfl_xor_sync(0xffffffffu, w, 2);
            w += __shfl_xor_sync(0xffffffffu, w, 1);
            if (lead) {
                if (qch == 0) S[(ii * NH + hsel) * NN + j] = w + b2h;
                else          S2t[(qch - 1) * 128 + (ii * NH + hsel) * JTILE + jj] = w;
            }
        }
        __syncthreads();
        // combine partials (deterministic)
        if (t < ITILE * NH * JTILE) {
            int r = t >> 4, jj = t & 15;
            S[r * NN + jt + jj] += S2t[t] + S2t[128 + t] + S2t[256 + t];
        }
        __syncthreads();
    }

    // =================== PASS 2: softmax (8 warps x 1 row) ===================
    {
        const int row = warp;                // 0..7 == rii*4 + h
        const int rii = row >> 2, h = row & 3;
        float vals[16];
        float m = NEGMAX;
        #pragma unroll
        for (int kk = 0; kk < 16; kk++) {
            vals[kk] = S[row * NN + lane + kk * 32];
            m = fmaxf(m, vals[kk]);
        }
        #pragma unroll
        for (int off = 16; off > 0; off >>= 1)
            m = fmaxf(m, __shfl_xor_sync(0xffffffffu, m, off));
        float sum = 0.f;
        #pragma unroll
        for (int kk = 0; kk < 16; kk++) {
            float p = __expf(vals[kk] - m);
            vals[kk] = p;
            sum += p;
        }
        #pragma unroll
        for (int off = 16; off > 0; off >>= 1)
            sum += __shfl_xor_sync(0xffffffffu, sum, off);
        const float inv = 1.0f / sum;
        float* arow = attn_out + (((size_t)b * NH + h) * NN + (i0 + rii)) * NN;
        #pragma unroll
        for (int kk = 0; kk < 16; kk++) {
            float a = vals[kk] * inv;
            S[row * NN + lane + kk * 32] = a;
            arow[lane + kk * 32] = a;
        }
    }
    __syncthreads();

    // =================== PASS 3: t and attn@v accumulation ===================
    #pragma unroll
    for (int c2 = 0; c2 < 2; c2++) {
        int cc = qch * 64 + lane + 32 * c2;
        b1r[c2] = bev1[cc];
        #pragma unroll
        for (int a = 0; a < EDIM; a++) W1r[a][c2] = Wev1[a * DIN + cc];
    }
    float tr[NH][2] = {};
    float va0 = 0.f, va1 = 0.f;   // this warp's head (=qch) v-accumulation

    for (int jt = 0; jt < NN; jt += JTILE) {
        {
            const float4* src = (const float4*)&g_v[(b * NN + jt) * DIN];
            float4* dst = (float4*)kvs;
            #pragma unroll
            for (int l = 0; l < 4; l++) dst[t + l * 256] = src[t + l * 256];
        }
        if (t < ITILE * JTILE * EDIM - 256 || t < 256) {
            for (int idx = t; idx < ITILE * JTILE * EDIM; idx += 256) {
                int r = idx / EDIM, a = idx - r * EDIM;
                int e_ii = r >> 4, jj = r & 15;
                esh[r * ESTRIDE + a] =
                    edge_attr[((size_t)(b * NN + i0 + e_ii) * NN + jt + jj) * EDIM + a];
            }
        }
        __syncthreads();

        for (int jj = 0; jj < JTILE; jj++) {
            const int j = jt + jj;
            float a4[NH];
            #pragma unroll
            for (int h = 0; h < NH; h++) a4[h] = S[(ii * NH + h) * NN + j];
            if (a4[0] + a4[1] + a4[2] + a4[3] == 0.f) continue;

            const float* er = esh + (ii * JTILE + jj) * ESTRIDE;
            float4 e0 = *(const float4*)er;
            float4 e1 = *(const float4*)(er + 4);
            float4 e2 = *(const float4*)(er + 8);
            float e[EDIM] = {e0.x, e0.y, e0.z, e0.w, e1.x, e1.y, e1.z, e1.w,
                             e2.x, e2.y, e2.z};

            #pragma unroll
            for (int c2 = 0; c2 < 2; c2++) {
                float s = b1r[c2];
                #pragma unroll
                for (int a = 0; a < EDIM; a++) s += e[a] * W1r[a][c2];
                float g = gelu_fast(s);
                #pragma unroll
                for (int h = 0; h < NH; h++) tr[h][c2] += a4[h] * g;
            }
            const float* vr = kvs + jj * DIN;
            va0 += a4[qch] * vr[qch * 64 + lane];
            va1 += a4[qch] * vr[qch * 64 + lane + 32];
        }
        __syncthreads();
    }

    // dump accumulators (disjoint smem regions; qs no longer needed)
    #pragma unroll
    for (int h = 0; h < NH; h++)
        #pragma unroll
        for (int c2 = 0; c2 < 2; c2++)
            tsh[(ii * NH + h) * DIN + qch * 64 + lane + 32 * c2] = tr[h][c2];
    vacc[ii * DIN + qch * 64 + lane]      = va0;
    vacc[ii * DIN + qch * 64 + lane + 32] = va1;
    __syncthreads();

    // =================== FINAL: o_inner = vacc + t@Wev2 + bev2 ===================
    {
        const int col = t;
        const int h = col >> 6;
        const float bcol = bev2[col];
        #pragma unroll
        for (int i2 = 0; i2 < ITILE; i2++) {
            const float* trow = &tsh[(i2 * NH + h) * DIN];
            float acc0 = 0.f, acc1 = 0.f, acc2 = 0.f, acc3 = 0.f;
            #pragma unroll 4
            for (int cc = 0; cc < DIN; cc += 4) {
                acc0 += trow[cc]     * Wev2[(cc)     * DIN + col];
                acc1 += trow[cc + 1] * Wev2[(cc + 1) * DIN + col];
                acc2 += trow[cc + 2] * Wev2[(cc + 2) * DIN + col];
                acc3 += trow[cc + 3] * Wev2[(cc + 3) * DIN + col];
            }
            g_oi[(b * NN + i0 + i2) * DIN + col] =
                ((acc0 + acc1) + (acc2 + acc3)) + vacc[i2 * DIN + col] + bcol;
        }
    }
}

// ============================================================
extern "C" void kernel_launch(void* const* d_in, const int* in_sizes, int n_in,
                              void* d_out, int out_size)
{
    const float* x           = (const float*)d_in[0];
    const void*  mask_raw    = d_in[1];
    const float* ea          = (const float*)d_in[2];
    const float* Wq          = (const float*)d_in[3];
    const float* Wk          = (const float*)d_in[4];
    const float* Wv          = (const float*)d_in[5];
    const float* Web1        = (const float*)d_in[6];
    const float* beb1        = (const float*)d_in[7];
    const float* Web2        = (const float*)d_in[8];
    const float* beb2        = (const float*)d_in[9];
    const float* Wev1        = (const float*)d_in[10];
    const float* bev1        = (const float*)d_in[11];
    const float* Wev2        = (const float*)d_in[12];
    const float* bev2        = (const float*)d_in[13];
    const float* Wo          = (const float*)d_in[14];
    const float* bo          = (const float*)d_in[15];

    float* out = (float*)d_out;
    const int out_elems  = BB * NN * QDIM;              // 524288
    const int attn_elems = BB * NH * NN * NN;           // 2097152
    const int mask_elems = BB * NN * NN;                // 524288

    float *oip, *attn_fb;
    unsigned char* maskp;
    cudaGetSymbolAddress((void**)&oip, g_oi);
    cudaGetSymbolAddress((void**)&attn_fb, g_attn_scratch);
    cudaGetSymbolAddress((void**)&maskp, g_mask);

    float* attn = (out_size >= out_elems + attn_elems) ? (out + out_elems) : attn_fb;

    const int smem_bytes = 47104;
    cudaFuncSetAttribute(attn_fused, cudaFuncAttributeMaxDynamicSharedMemorySize, smem_bytes);

    // mask canonicalize (detection embedded per block)
    canon_mask_kernel<<<256, 256>>>((const unsigned int*)mask_raw, mask_elems);

    // fused q/k/v projections: 3 x 8 x 16 = 384 blocks
    qkv_gemm<<<dim3(24, (BB * NN) / 64), 256>>>(x, Wq, Wk, Wv);

    // fused attention + edge MLPs (256 thr, 4 blocks/SM, 512 blocks)
    attn_fused<<<dim3(NN / ITILE, BB), 256, smem_bytes>>>(
        ea, maskp, Web1, beb1, Web2, beb2, Wev1, bev1, Wev2, bev2, attn);

    // final projection: out = o_inner @ Wo + bo
    gemm_tiled<<<dim3(QDIM / 32, (BB * NN) / 64), 256>>>(oip, Wo, bo, out, BB * NN, DIN, QDIM);
}

// round 8
// speedup vs baseline: 2.5749x; 1.2481x over previous
#include <cuda_runtime.h>
#include <math.h>

#define BB 2
#define NN 512
#define QDIM 512
#define EDIM 11
#define NH 4
#define DHEAD 64
#define DIN 256          // INNER = NH*DHEAD
#define SCALE_F 0.125f   // 64^-0.5
#define NEGMAX -3.402823466e38f

#define ITILE 4
#define JTILE 32
#define ESTRIDE 12       // padded edge-feature row stride (16B-aligned float4 loads)

// -------- device scratch (no allocations allowed) --------
__device__ float g_q[BB * NN * DIN];
__device__ float g_k[BB * NN * DIN];
__device__ float g_v[BB * NN * DIN];
__device__ float g_oi[BB * NN * DIN];
__device__ float g_attn_scratch[BB * NH * NN * NN];
__device__ unsigned char g_mask[BB * NN * NN];

typedef unsigned long long u64;

// ---- packed fp32x2 helpers (Blackwell; ptxas never emits these itself) ----
__device__ __forceinline__ u64 pack2(float lo, float hi) {
    u64 r; asm("mov.b64 %0, {%1, %2};" : "=l"(r) : "f"(lo), "f"(hi)); return r;
}
__device__ __forceinline__ void unpack2(u64 v, float& lo, float& hi) {
    asm("mov.b64 {%0, %1}, %2;" : "=f"(lo), "=f"(hi) : "l"(v));
}
__device__ __forceinline__ u64 fma2(u64 a, u64 b, u64 c) {
    u64 d; asm("fma.rn.f32x2 %0, %1, %2, %3;" : "=l"(d) : "l"(a), "l"(b), "l"(c)); return d;
}

// lean fast GELU: u = x*(c1 + c2*x^2); g = 0.5x + 0.5x*tanh(u). 5 inst + MUFU.
__device__ __forceinline__ float gelu_fast(float x) {
    float x2 = x * x;
    float u = x * fmaf(0.0356774081f, x2, 0.7978845608f);
    float th;
    asm("tanh.approx.f32 %0, %1;" : "=f"(th) : "f"(u));
    float hx = 0.5f * x;
    return fmaf(hx, th, hx);
}

// ============================================================
// Mask canonicalization with embedded dtype detection (proven R7).
// ============================================================
__global__ __launch_bounds__(256) void canon_mask_kernel(
    const unsigned int* __restrict__ raw, int n)
{
    int weird = 0, flt = 0;
    for (int i = threadIdx.x; i < 4096; i += 256) {
        unsigned int v = raw[i];
        if (v == 0x3F800000u) flt = 1;
        else if (v > 1u) weird = 1;
    }
    weird = __syncthreads_or(weird);
    flt   = __syncthreads_or(flt);
    const int mode = weird ? 2 : (flt ? 1 : 0);

    for (int i = blockIdx.x * blockDim.x + threadIdx.x; i < n; i += gridDim.x * blockDim.x) {
        unsigned char m;
        if (mode == 2)      m = (((const unsigned char*)raw)[i] != 0);
        else if (mode == 1) m = (((const float*)raw)[i] != 0.0f);
        else                m = (raw[i] != 0u);
        g_mask[i] = m;
    }
}

// ============================================================
// GEMM 64x32 tile, 256 threads, 4x2 per thread, K-tile 16.
// ============================================================
__device__ __forceinline__ void gemm_body(
    const float* __restrict__ A, const float* __restrict__ W,
    const float* __restrict__ bias, float* __restrict__ C,
    int M, int K, int Nc, int m0, int n0)
{
    __shared__ float As[16][65];
    __shared__ float Bs[16][33];
    const int t = threadIdx.x;
    const int r = t >> 4, c = t & 15;
    float acc[4][2] = {};

    for (int k0 = 0; k0 < K; k0 += 16) {
        #pragma unroll
        for (int l = 0; l < 4; l++) {
            int idx = t + l * 256;
            int mm = idx >> 4, kk = idx & 15;
            As[kk][mm] = A[(m0 + mm) * K + (k0 + kk)];
        }
        #pragma unroll
        for (int l = 0; l < 2; l++) {
            int idx = t + l * 256;
            int kk = idx >> 5, nn = idx & 31;
            Bs[kk][nn] = W[(k0 + kk) * Nc + (n0 + nn)];
        }
        __syncthreads();
        #pragma unroll
        for (int kk = 0; kk < 16; kk++) {
            float av[4], bv[2];
            #pragma unroll
            for (int l = 0; l < 4; l++) av[l] = As[kk][r * 4 + l];
            bv[0] = Bs[kk][c * 2];
            bv[1] = Bs[kk][c * 2 + 1];
            #pragma unroll
            for (int i = 0; i < 4; i++) {
                acc[i][0] += av[i] * bv[0];
                acc[i][1] += av[i] * bv[1];
            }
        }
        __syncthreads();
    }

    #pragma unroll
    for (int i = 0; i < 4; i++)
        #pragma unroll
        for (int j = 0; j < 2; j++) {
            int m = m0 + r * 4 + i, n = n0 + c * 2 + j;
            float v = acc[i][j];
            if (bias) v += bias[n];
            C[m * Nc + n] = v;
        }
}

__global__ __launch_bounds__(256) void qkv_gemm(
    const float* __restrict__ x,
    const float* __restrict__ Wq, const float* __restrict__ Wk, const float* __restrict__ Wv)
{
    const int sel = blockIdx.x >> 3;
    const int n0 = (blockIdx.x & 7) * 32;
    const int m0 = blockIdx.y * 64;
    const float* W = (sel == 0) ? Wq : (sel == 1) ? Wk : Wv;
    float* C = (sel == 0) ? g_q : (sel == 1) ? g_k : g_v;
    gemm_body(x, W, nullptr, C, BB * NN, QDIM, DIN, m0, n0);
}

__global__ __launch_bounds__(256) void gemm_tiled(
    const float* __restrict__ A, const float* __restrict__ W,
    const float* __restrict__ bias, float* __restrict__ C,
    int M, int K, int Nc)
{
    gemm_body(A, W, bias, C, M, K, Nc, blockIdx.y * 64, blockIdx.x * 32);
}

// ============================================================
// Fused attention: block = (b, 4 query rows), 256 threads, 2 blocks/SM.
// Two warps per query row split the 256 MLP channels; MLP first-layer
// chains run in packed fp32x2 (channel pairs).
// ============================================================
__global__ __launch_bounds__(256, 2) void attn_fused(
    const float* __restrict__ edge_attr,
    const unsigned char* __restrict__ mask,
    const float* __restrict__ Web1, const float* __restrict__ beb1,
    const float* __restrict__ Web2, const float* __restrict__ beb2,
    const float* __restrict__ Wev1, const float* __restrict__ bev1,
    const float* __restrict__ Wev2, const float* __restrict__ bev2,
    float* __restrict__ attn_out)
{
    extern __shared__ float sm[];
    float* qs   = sm;                  // 1024   (4*256)
    float* S    = sm + 1024;           // 8192   (4 rows * 4 heads * 512)
    float* tsh  = sm + 9216;           // 4096   (4*4*256)
    float* vacc = sm + 13312;          // 1024
    float* esh  = sm + 14336;          // 1536   (4*32*ESTRIDE)
    float* kvs  = sm + 15872;          // 8192   (32*256)
    float* S2t  = sm + 24064;          // 512    (4*4*32)
    unsigned char* msh = (unsigned char*)(sm + 24576);  // 2048 bytes
    // total 25088 floats = 100352 bytes

    const int t = threadIdx.x;
    const int warp = t >> 5, lane = t & 31;
    const int b = blockIdx.y;
    const int i0 = blockIdx.x * ITILE;
    const int ii = warp >> 1;   // query row in tile (0..3)
    const int ch = warp & 1;    // channel half
    const int hsel = lane >> 3; // head this lane finalizes
    const int lead = ((lane & 7) == 0);

    // ---- stage q rows + mask rows ----
    ((float4*)qs)[t] = ((const float4*)&g_q[(b * NN + i0) * DIN])[t];
    {
        const unsigned int* msrc = (const unsigned int*)&mask[(b * NN + i0) * NN];
        unsigned int* mdst = (unsigned int*)msh;
        mdst[t] = msrc[t];
        mdst[t + 256] = msrc[t + 256];
    }

    // ---- per-lane packed weights: pair p covers channels (64p, 64p+32) within half ----
    u64 W1p[EDIM][2], b1p[2];
    float W2r[4][4];
    #pragma unroll
    for (int p = 0; p < 2; p++) {
        int cc0 = ch * 128 + lane + 64 * p;
        int cc1 = cc0 + 32;
        b1p[p] = pack2(beb1[cc0], beb1[cc1]);
        #pragma unroll
        for (int a = 0; a < EDIM; a++)
            W1p[a][p] = pack2(Web1[a * DIN + cc0], Web1[a * DIN + cc1]);
    }
    #pragma unroll
    for (int c4 = 0; c4 < 4; c4++) {
        int cc = ch * 128 + lane + 32 * ((c4 & 1) ? (2 * (c4 >> 1) + 1) : (2 * (c4 >> 1)));
        // map: c4 index below uses order [p0_lo, p0_hi, p1_lo, p1_hi]
        (void)cc;
    }
    // W2 in chain-pair order: idx 0..3 = (p0 lo, p0 hi, p1 lo, p1 hi)
    #pragma unroll
    for (int idx4 = 0; idx4 < 4; idx4++) {
        int p = idx4 >> 1, hi = idx4 & 1;
        int cc = ch * 128 + lane + 64 * p + 32 * hi;
        #pragma unroll
        for (int h = 0; h < NH; h++) W2r[idx4][h] = Web2[cc * NH + h];
    }
    const float b2h = beb2[hsel];
    __syncthreads();

    // hoist this row's q into registers (ch==0 warps compute qk)
    float qreg[NH][2];
    if (ch == 0) {
        #pragma unroll
        for (int h = 0; h < NH; h++) {
            qreg[h][0] = qs[ii * DIN + h * 64 + lane];
            qreg[h][1] = qs[ii * DIN + h * 64 + lane + 32];
        }
    }

    // =================== PASS 1: sim + edge bias ===================
    for (int jt = 0; jt < NN; jt += JTILE) {
        {
            const float4* src = (const float4*)&g_k[(b * NN + jt) * DIN];
            float4* dst = (float4*)kvs;
            #pragma unroll
            for (int l = 0; l < 8; l++) dst[t + l * 256] = src[t + l * 256];
        }
        for (int idx = t; idx < ITILE * JTILE * EDIM; idx += 256) {
            int r = idx / EDIM, a = idx - r * EDIM;
            int e_ii = r >> 5, jj = r & 31;
            esh[r * ESTRIDE + a] =
                edge_attr[((size_t)(b * NN + i0 + e_ii) * NN + jt + jj) * EDIM + a];
        }
        __syncthreads();

        for (int jj = 0; jj < JTILE; jj++) {
            const int j = jt + jj;
            if (!msh[ii * NN + j]) {
                if (lead) {
                    if (ch == 0) S[(ii * NH + hsel) * NN + j] = NEGMAX;
                    else         S2t[(ii * NH + hsel) * JTILE + jj] = 0.f;
                }
                continue;
            }
            const float* er = esh + (ii * JTILE + jj) * ESTRIDE;
            float4 ef0 = *(const float4*)er;
            float4 ef1 = *(const float4*)(er + 4);
            float4 ef2 = *(const float4*)(er + 8);
            float e[EDIM] = {ef0.x, ef0.y, ef0.z, ef0.w, ef1.x, ef1.y, ef1.z, ef1.w,
                             ef2.x, ef2.y, ef2.z};

            float red0, red1, red2, red3;
            if (ch == 0) {
                const float* kr = kvs + jj * DIN;
                red0 = SCALE_F * (qreg[0][0] * kr[lane] + qreg[0][1] * kr[lane + 32]);
                red1 = SCALE_F * (qreg[1][0] * kr[64 + lane] + qreg[1][1] * kr[96 + lane]);
                red2 = SCALE_F * (qreg[2][0] * kr[128 + lane] + qreg[2][1] * kr[160 + lane]);
                red3 = SCALE_F * (qreg[3][0] * kr[192 + lane] + qreg[3][1] * kr[224 + lane]);
            } else {
                red0 = red1 = red2 = red3 = 0.f;
            }

            // packed dual-channel MLP chains
            u64 s2a = b1p[0], s2b = b1p[1];
            #pragma unroll
            for (int a = 0; a < EDIM; a++) {
                u64 ea = pack2(e[a], e[a]);
                s2a = fma2(ea, W1p[a][0], s2a);
                s2b = fma2(ea, W1p[a][1], s2b);
            }
            float sA, sB, sC, sD;
            unpack2(s2a, sA, sB);
            unpack2(s2b, sC, sD);
            float gA = gelu_fast(sA), gB = gelu_fast(sB);
            float gC = gelu_fast(sC), gD = gelu_fast(sD);
            red0 = fmaf(gA, W2r[0][0], fmaf(gB, W2r[1][0], fmaf(gC, W2r[2][0], fmaf(gD, W2r[3][0], red0))));
            red1 = fmaf(gA, W2r[0][1], fmaf(gB, W2r[1][1], fmaf(gC, W2r[2][1], fmaf(gD, W2r[3][1], red1))));
            red2 = fmaf(gA, W2r[0][2], fmaf(gB, W2r[1][2], fmaf(gC, W2r[2][2], fmaf(gD, W2r[3][2], red2))));
            red3 = fmaf(gA, W2r[0][3], fmaf(gB, W2r[1][3], fmaf(gC, W2r[2][3], fmaf(gD, W2r[3][3], red3))));

            #pragma unroll
            for (int off = 16; off >= 8; off >>= 1) {
                red0 += __shfl_xor_sync(0xffffffffu, red0, off);
                red1 += __shfl_xor_sync(0xffffffffu, red1, off);
                red2 += __shfl_xor_sync(0xffffffffu, red2, off);
                red3 += __shfl_xor_sync(0xffffffffu, red3, off);
            }
            float w = (hsel == 0) ? red0 : (hsel == 1) ? red1 : (hsel == 2) ? red2 : red3;
            w += __shfl_xor_sync(0xffffffffu, w, 4);
            w += __shfl_xor_sync(0xffffffffu, w, 2);
            w += __shfl_xor_sync(0xffffffffu, w, 1);
            if (lead) {
                if (ch == 0) S[(ii * NH + hsel) * NN + j] = w + b2h;
                else         S2t[(ii * NH + hsel) * JTILE + jj] = w;
            }
        }
        __syncthreads();
        // combine ch1 partials into S (deterministic)
        for (int idx = t; idx < ITILE * NH * JTILE; idx += 256) {
            int r = idx >> 5, jj = idx & 31;
            S[r * NN + jt + jj] += S2t[idx];
        }
        __syncthreads();
    }

    // =================== PASS 2: softmax (8 warps x 2 rows) ===================
    #pragma unroll
    for (int rr = 0; rr < 2; rr++) {
        const int row = warp * 2 + rr;       // 0..15 == rii*4 + h
        const int rii = row >> 2, h = row & 3;
        float vals[16];
        float m = NEGMAX;
        #pragma unroll
        for (int kk = 0; kk < 16; kk++) {
            vals[kk] = S[row * NN + lane + kk * 32];
            m = fmaxf(m, vals[kk]);
        }
        #pragma unroll
        for (int off = 16; off > 0; off >>= 1)
            m = fmaxf(m, __shfl_xor_sync(0xffffffffu, m, off));
        float sum = 0.f;
        #pragma unroll
        for (int kk = 0; kk < 16; kk++) {
            float p = __expf(vals[kk] - m);
            vals[kk] = p;
            sum += p;
        }
        #pragma unroll
        for (int off = 16; off > 0; off >>= 1)
            sum += __shfl_xor_sync(0xffffffffu, sum, off);
        const float inv = 1.0f / sum;
        float* arow = attn_out + (((size_t)b * NH + h) * NN + (i0 + rii)) * NN;
        #pragma unroll
        for (int kk = 0; kk < 16; kk++) {
            float a = vals[kk] * inv;
            S[row * NN + lane + kk * 32] = a;
            arow[lane + kk * 32] = a;
        }
    }
    __syncthreads();

    // =================== PASS 3: t and attn@v accumulation ===================
    #pragma unroll
    for (int p = 0; p < 2; p++) {
        int cc0 = ch * 128 + lane + 64 * p;
        int cc1 = cc0 + 32;
        b1p[p] = pack2(bev1[cc0], bev1[cc1]);
        #pragma unroll
        for (int a = 0; a < EDIM; a++)
            W1p[a][p] = pack2(Wev1[a * DIN + cc0], Wev1[a * DIN + cc1]);
    }
    u64 tr2[NH][2];
    #pragma unroll
    for (int h = 0; h < NH; h++) { tr2[h][0] = 0ull; tr2[h][1] = 0ull; }
    float va[2][2] = {};

    for (int jt = 0; jt < NN; jt += JTILE) {
        {
            const float4* src = (const float4*)&g_v[(b * NN + jt) * DIN];
            float4* dst = (float4*)kvs;
            #pragma unroll
            for (int l = 0; l < 8; l++) dst[t + l * 256] = src[t + l * 256];
        }
        for (int idx = t; idx < ITILE * JTILE * EDIM; idx += 256) {
            int r = idx / EDIM, a = idx - r * EDIM;
            int e_ii = r >> 5, jj = r & 31;
            esh[r * ESTRIDE + a] =
                edge_attr[((size_t)(b * NN + i0 + e_ii) * NN + jt + jj) * EDIM + a];
        }
        __syncthreads();

        for (int jj = 0; jj < JTILE; jj++) {
            const int j = jt + jj;
            float a4[NH];
            #pragma unroll
            for (int h = 0; h < NH; h++) a4[h] = S[(ii * NH + h) * NN + j];
            if (a4[0] + a4[1] + a4[2] + a4[3] == 0.f) continue;  // masked: exact zeros

            const float* er = esh + (ii * JTILE + jj) * ESTRIDE;
            float4 ef0 = *(const float4*)er;
            float4 ef1 = *(const float4*)(er + 4);
            float4 ef2 = *(const float4*)(er + 8);
            float e[EDIM] = {ef0.x, ef0.y, ef0.z, ef0.w, ef1.x, ef1.y, ef1.z, ef1.w,
                             ef2.x, ef2.y, ef2.z};

            u64 s2a = b1p[0], s2b = b1p[1];
            #pragma unroll
            for (int a = 0; a < EDIM; a++) {
                u64 ea = pack2(e[a], e[a]);
                s2a = fma2(ea, W1p[a][0], s2a);
                s2b = fma2(ea, W1p[a][1], s2b);
            }
            float sA, sB, sC, sD;
            unpack2(s2a, sA, sB);
            unpack2(s2b, sC, sD);
            u64 g2a = pack2(gelu_fast(sA), gelu_fast(sB));
            u64 g2b = pack2(gelu_fast(sC), gelu_fast(sD));
            #pragma unroll
            for (int h = 0; h < NH; h++) {
                u64 ah = pack2(a4[h], a4[h]);
                tr2[h][0] = fma2(ah, g2a, tr2[h][0]);
                tr2[h][1] = fma2(ah, g2b, tr2[h][1]);
            }
            const float* vr = kvs + jj * DIN;
            #pragma unroll
            for (int hh = 0; hh < 2; hh++) {
                const int h = ch * 2 + hh;
                va[hh][0] += a4[h] * vr[h * 64 + lane];
                va[hh][1] += a4[h] * vr[h * 64 + lane + 32];
            }
        }
        __syncthreads();
    }

    // dump accumulators (chain-pair order: p0_lo, p0_hi, p1_lo, p1_hi)
    #pragma unroll
    for (int h = 0; h < NH; h++) {
        float tA, tB, tC, tD;
        unpack2(tr2[h][0], tA, tB);
        unpack2(tr2[h][1], tC, tD);
        float* trow = &tsh[(ii * NH + h) * DIN + ch * 128 + lane];
        trow[0]  = tA;
        trow[32] = tB;
        trow[64] = tC;
        trow[96] = tD;
    }
    #pragma unroll
    for (int hh = 0; hh < 2; hh++) {
        const int h = ch * 2 + hh;
        vacc[ii * DIN + h * 64 + lane]      = va[hh][0];
        vacc[ii * DIN + h * 64 + lane + 32] = va[hh][1];
    }
    __syncthreads();

    // =================== FINAL: o_inner = vacc + t@Wev2 + bev2 ===================
    {
        const int col = t;
        const int h = col >> 6;
        const float bcol = bev2[col];
        #pragma unroll
        for (int i2 = 0; i2 < ITILE; i2++) {
            const float* trow = &tsh[(i2 * NH + h) * DIN];
            float acc0 = 0.f, acc1 = 0.f, acc2 = 0.f, acc3 = 0.f;
            #pragma unroll 4
            for (int cc = 0; cc < DIN; cc += 4) {
                acc0 += trow[cc]     * Wev2[(cc)     * DIN + col];
                acc1 += trow[cc + 1] * Wev2[(cc + 1) * DIN + col];
                acc2 += trow[cc + 2] * Wev2[(cc + 2) * DIN + col];
                acc3 += trow[cc + 3] * Wev2[(cc + 3) * DIN + col];
            }
            g_oi[(b * NN + i0 + i2) * DIN + col] =
                ((acc0 + acc1) + (acc2 + acc3)) + vacc[i2 * DIN + col] + bcol;
        }
    }
}

// ============================================================
extern "C" void kernel_launch(void* const* d_in, const int* in_sizes, int n_in,
                              void* d_out, int out_size)
{
    const float* x           = (const float*)d_in[0];
    const void*  mask_raw    = d_in[1];
    const float* ea          = (const float*)d_in[2];
    const float* Wq          = (const float*)d_in[3];
    const float* Wk          = (const float*)d_in[4];
    const float* Wv          = (const float*)d_in[5];
    const float* Web1        = (const float*)d_in[6];
    const float* beb1        = (const float*)d_in[7];
    const float* Web2        = (const float*)d_in[8];
    const float* beb2        = (const float*)d_in[9];
    const float* Wev1        = (const float*)d_in[10];
    const float* bev1        = (const float*)d_in[11];
    const float* Wev2        = (const float*)d_in[12];
    const float* bev2        = (const float*)d_in[13];
    const float* Wo          = (const float*)d_in[14];
    const float* bo          = (const float*)d_in[15];

    float* out = (float*)d_out;
    const int out_elems  = BB * NN * QDIM;              // 524288
    const int attn_elems = BB * NH * NN * NN;           // 2097152
    const int mask_elems = BB * NN * NN;                // 524288

    float *oip, *attn_fb;
    unsigned char* maskp;
    cudaGetSymbolAddress((void**)&oip, g_oi);
    cudaGetSymbolAddress((void**)&attn_fb, g_attn_scratch);
    cudaGetSymbolAddress((void**)&maskp, g_mask);

    float* attn = (out_size >= out_elems + attn_elems) ? (out + out_elems) : attn_fb;

    const int smem_bytes = 25088 * 4;   // 100352
    cudaFuncSetAttribute(attn_fused, cudaFuncAttributeMaxDynamicSharedMemorySize, smem_bytes);

    // mask canonicalize (dtype detection embedded)
    canon_mask_kernel<<<256, 256>>>((const unsigned int*)mask_raw, mask_elems);

    // fused q/k/v projections: 3 x 8 x 16 = 384 blocks
    qkv_gemm<<<dim3(24, (BB * NN) / 64), 256>>>(x, Wq, Wk, Wv);

    // fused attention + edge MLPs (256 thr, 2 blocks/SM, 256 blocks)
    attn_fused<<<dim3(NN / ITILE, BB), 256, smem_bytes>>>(
        ea, maskp, Web1, beb1, Web2, beb2, Wev1, bev1, Wev2, bev2, attn);

    // final projection: out = o_inner @ Wo + bo
    gemm_tiled<<<dim3(QDIM / 32, (BB * NN) / 64), 256>>>(oip, Wo, bo, out, BB * NN, DIN, QDIM);
}